// round 1
// baseline (speedup 1.0000x reference)
#include <cuda_runtime.h>

#define NN 100000
#define EE 1600000
#define DIN_ 32
#define HH 64
#define GG 128
#define OUTC 10

// ---------------- scratch (static device globals; no runtime alloc) ----------------
__device__ float g_h[(size_t)NN * HH];     // layer input / BN output
__device__ float g_agg[(size_t)NN * HH];   // aggregation accumulator (init = x)
__device__ float g_h1[(size_t)NN * HH];    // GEMM1 intermediate
__device__ float g_stats[4 * 2 * HH];      // per-layer BN sums/sumsq
__device__ float g_pool[GG * HH];
__device__ float g_cnt[GG];

// ---------------- helpers ----------------
__device__ __forceinline__ void atomic_add4(float* p, float4 v) {
#if __CUDA_ARCH__ >= 900
    atomicAdd(reinterpret_cast<float4*>(p), v);
#else
    atomicAdd(p + 0, v.x); atomicAdd(p + 1, v.y);
    atomicAdd(p + 2, v.z); atomicAdd(p + 3, v.w);
#endif
}

// ---------------- init: agg = x (layer0, C=32), zero pool/cnt/stats ----------------
__global__ void init_kernel(const float* __restrict__ x) {
    int i = blockIdx.x * blockDim.x + threadIdx.x;
    int stride = gridDim.x * blockDim.x;
    for (int idx = i; idx < NN * DIN_; idx += stride) g_agg[idx] = x[idx];
    if (i < GG * HH) g_pool[i] = 0.f;
    if (i < GG) g_cnt[i] = 0.f;
    if (i < 4 * 2 * HH) g_stats[i] = 0.f;
}

// ---------------- edge kernel: m = relu(x[src] + ea @ ew^T + eb); agg[dst] += m ----
// Block covers EB edges x C channels. Thread owns 2 edges x 4 channels.
// ea held in registers (32 regs), weights transposed in smem: 8 FMA per LDS.128.
template <int C>
__global__ void __launch_bounds__(256) edge_kernel(
    const float* __restrict__ xin, const int* __restrict__ eidx,
    const float* __restrict__ ea, const float* __restrict__ ew,
    const float* __restrict__ ebv, float* __restrict__ agg)
{
    constexpr int CG = C / 4;         // channel groups (threads per edge-pair)
    constexpr int EP = 256 / CG;      // edge pairs per block
    constexpr int EB = 2 * EP;        // edges per block
    __shared__ __align__(16) float ea_s[EB * 16];
    __shared__ __align__(16) float wt_s[16 * C];   // [k][c] transposed
    __shared__ float eb_s[C];

    int t = threadIdx.x;
    int e_base = blockIdx.x * EB;

    for (int i = t; i < C * 16; i += 256) { int c = i >> 4, k = i & 15; wt_s[k * C + c] = ew[i]; }
    if (t < C) eb_s[t] = ebv[t];
    for (int i = t; i < EB * 4; i += 256) {
        int e = e_base + (i >> 2);
        float4 v = (e < EE) ? ((const float4*)ea)[(e << 2) + (i & 3)] : make_float4(0.f, 0.f, 0.f, 0.f);
        ((float4*)ea_s)[i] = v;
    }
    __syncthreads();

    int tx = t % CG;
    int ep = t / CG;
    int c0 = tx * 4;
    int e0 = e_base + ep * 2;

    float4 A0[4], A1[4];
#pragma unroll
    for (int q = 0; q < 4; q++) {
        A0[q] = ((const float4*)ea_s)[ep * 8 + q];
        A1[q] = ((const float4*)ea_s)[ep * 8 + 4 + q];
    }
    float acc0[4], acc1[4];
#pragma unroll
    for (int j = 0; j < 4; j++) { float b = eb_s[c0 + j]; acc0[j] = b; acc1[j] = b; }

#pragma unroll
    for (int kk = 0; kk < 4; kk++) {
        float a0v[4] = {A0[kk].x, A0[kk].y, A0[kk].z, A0[kk].w};
        float a1v[4] = {A1[kk].x, A1[kk].y, A1[kk].z, A1[kk].w};
#pragma unroll
        for (int r = 0; r < 4; r++) {
            float4 w = *(const float4*)&wt_s[(kk * 4 + r) * C + c0];
            acc0[0] = fmaf(a0v[r], w.x, acc0[0]); acc0[1] = fmaf(a0v[r], w.y, acc0[1]);
            acc0[2] = fmaf(a0v[r], w.z, acc0[2]); acc0[3] = fmaf(a0v[r], w.w, acc0[3]);
            acc1[0] = fmaf(a1v[r], w.x, acc1[0]); acc1[1] = fmaf(a1v[r], w.y, acc1[1]);
            acc1[2] = fmaf(a1v[r], w.z, acc1[2]); acc1[3] = fmaf(a1v[r], w.w, acc1[3]);
        }
    }

    if (e0 < EE) {
        int s0 = eidx[e0], d0 = eidx[EE + e0];
        float4 xs = *(const float4*)&xin[s0 * C + c0];
        float4 m = make_float4(fmaxf(acc0[0] + xs.x, 0.f), fmaxf(acc0[1] + xs.y, 0.f),
                               fmaxf(acc0[2] + xs.z, 0.f), fmaxf(acc0[3] + xs.w, 0.f));
        atomic_add4(&agg[d0 * C + c0], m);
    }
    if (e0 + 1 < EE) {
        int s1 = eidx[e0 + 1], d1 = eidx[EE + e0 + 1];
        float4 xs = *(const float4*)&xin[s1 * C + c0];
        float4 m = make_float4(fmaxf(acc1[0] + xs.x, 0.f), fmaxf(acc1[1] + xs.y, 0.f),
                               fmaxf(acc1[2] + xs.z, 0.f), fmaxf(acc1[3] + xs.w, 0.f));
        atomic_add4(&agg[d1 * C + c0], m);
    }
}

// ---------------- node GEMM: out[n][c]=relu(sum_k in[n][k]*w[c][k] + b[c]), 64 out ch
// Tile 64 nodes; thread owns 4 nodes x 4 (interleaved) channels.
template <int K>
__global__ void __launch_bounds__(256) gemm_relu_kernel(
    const float* __restrict__ in, const float* __restrict__ w,
    const float* __restrict__ bias, float* __restrict__ out)
{
    __shared__ __align__(16) float in_s[64][K + 4];
    __shared__ __align__(16) float w_s[64][K + 4];
    constexpr int K4 = K / 4;
    int t = threadIdx.x;
    int n0 = blockIdx.x * 64;

    for (int i = t; i < 64 * K4; i += 256) {
        int r = i / K4, c4 = i % K4;
        *(float4*)&w_s[r][c4 * 4] = ((const float4*)w)[i];
        int n = n0 + r;
        float4 v = (n < NN) ? ((const float4*)in)[n * K4 + c4] : make_float4(0.f, 0.f, 0.f, 0.f);
        *(float4*)&in_s[r][c4 * 4] = v;
    }
    __syncthreads();

    int tx = t & 15, ty = t >> 4;
    float acc[4][4] = {};
#pragma unroll
    for (int k = 0; k < K; k += 4) {
        float4 a[4], b[4];
#pragma unroll
        for (int i = 0; i < 4; i++) a[i] = *(const float4*)&in_s[ty * 4 + i][k];
#pragma unroll
        for (int j = 0; j < 4; j++) b[j] = *(const float4*)&w_s[tx + j * 16][k];
#pragma unroll
        for (int i = 0; i < 4; i++)
#pragma unroll
            for (int j = 0; j < 4; j++)
                acc[i][j] = fmaf(a[i].x, b[j].x, fmaf(a[i].y, b[j].y,
                             fmaf(a[i].z, b[j].z, fmaf(a[i].w, b[j].w, acc[i][j]))));
    }
#pragma unroll
    for (int j = 0; j < 4; j++) {
        int c = tx + j * 16;
        float bb = bias[c];
#pragma unroll
        for (int i = 0; i < 4; i++) {
            int n = n0 + ty * 4 + i;
            if (n < NN) out[n * 64 + c] = fmaxf(acc[i][j] + bb, 0.f);
        }
    }
}

// ---------------- BN stats: per-channel sum & sumsq ----------------
__global__ void bn_stats_kernel(const float* __restrict__ h, float* __restrict__ stats) {
    int t = threadIdx.x;
    int c = t & 63, r = t >> 6;
    float s = 0.f, q = 0.f;
    for (int n = blockIdx.x * 4 + r; n < NN; n += gridDim.x * 4) {
        float v = h[n * 64 + c];
        s += v; q = fmaf(v, v, q);
    }
    __shared__ float sh[256], qh[256];
    sh[t] = s; qh[t] = q;
    __syncthreads();
    if (t < 64) {
        float S = sh[t] + sh[t + 64] + sh[t + 128] + sh[t + 192];
        float Q = qh[t] + qh[t + 64] + qh[t + 128] + qh[t + 192];
        atomicAdd(&stats[t], S);
        atomicAdd(&stats[64 + t], Q);
    }
}

// ---------------- BN apply + relu; also writes next layer's agg init -------------
__global__ void bn_apply_kernel(float* __restrict__ h, const float* __restrict__ stats,
                                const float* __restrict__ gamma, const float* __restrict__ beta,
                                float* __restrict__ agg_out) {
    __shared__ float sc[64], sf[64];
    int t = threadIdx.x;
    if (t < 64) {
        float mu = stats[t] * (1.0f / NN);
        float var = stats[64 + t] * (1.0f / NN) - mu * mu;
        float inv = rsqrtf(var + 1e-5f);
        float g = gamma[t], b = beta[t];
        sc[t] = inv * g;
        sf[t] = b - mu * inv * g;
    }
    __syncthreads();
    int i0 = blockIdx.x * blockDim.x + t;
    for (int i = i0; i < NN * 64; i += gridDim.x * blockDim.x) {
        int c = i & 63;
        float v = fmaxf(fmaf(h[i], sc[c], sf[c]), 0.f);
        h[i] = v;
        if (agg_out) agg_out[i] = v;
    }
}

// ---------------- global mean pool (atomic sums + counts) ----------------
__global__ void pool_kernel(const float* __restrict__ h, const int* __restrict__ batch) {
    int t = blockIdx.x * blockDim.x + threadIdx.x;
    int n = t >> 2, q = t & 3;
    if (n >= NN) return;
    int b = batch[n];
#pragma unroll
    for (int k = 0; k < 4; k++) {
        float4 v = ((const float4*)h)[n * 16 + q * 4 + k];
        atomic_add4(&g_pool[b * 64 + (q * 4 + k) * 4], v);
    }
    if (q == 0) atomicAdd(&g_cnt[b], 1.0f);
}

// ---------------- MLP head ----------------
__global__ void head_kernel(const float* __restrict__ hw1, const float* __restrict__ hb1,
                            const float* __restrict__ hw2, const float* __restrict__ hb2,
                            float* __restrict__ out) {
    int g = blockIdx.x, t = threadIdx.x;
    __shared__ float p[64];
    __shared__ float z[128];
    if (t < 64) {
        float c = g_cnt[g];
        p[t] = g_pool[g * 64 + t] / fmaxf(c, 1.0f);
    }
    __syncthreads();
    float s = hb1[t];
#pragma unroll 8
    for (int k = 0; k < 64; k++) s = fmaf(p[k], hw1[t * 64 + k], s);
    z[t] = fmaxf(s, 0.f);
    __syncthreads();
    if (t < OUTC) {
        float s2 = hb2[t];
#pragma unroll 8
        for (int k = 0; k < 128; k++) s2 = fmaf(z[k], hw2[t * 128 + k], s2);
        out[g * OUTC + t] = s2;
    }
}

// ---------------- launch ----------------
extern "C" void kernel_launch(void* const* d_in, const int* in_sizes, int n_in,
                              void* d_out, int out_size) {
    const float* x     = (const float*)d_in[0];
    const int*   eidx  = (const int*)  d_in[1];
    const float* ea    = (const float*)d_in[2];
    const int*   batch = (const int*)  d_in[3];
    const float* l0_ew = (const float*)d_in[4];
    const float* l0_eb = (const float*)d_in[5];
    const float* l0_w1 = (const float*)d_in[6];
    const float* l0_b1 = (const float*)d_in[7];
    const float* l0_w2 = (const float*)d_in[8];
    const float* l0_b2 = (const float*)d_in[9];
    const float* ew    = (const float*)d_in[10];
    const float* eb    = (const float*)d_in[11];
    const float* w1    = (const float*)d_in[12];
    const float* b1    = (const float*)d_in[13];
    const float* w2    = (const float*)d_in[14];
    const float* b2    = (const float*)d_in[15];
    const float* gam   = (const float*)d_in[16];
    const float* bet   = (const float*)d_in[17];
    const float* hw1   = (const float*)d_in[18];
    const float* hb1   = (const float*)d_in[19];
    const float* hw2   = (const float*)d_in[20];
    const float* hb2   = (const float*)d_in[21];
    float* out = (float*)d_out;

    float *hp, *aggp, *h1p, *statsp;
    cudaGetSymbolAddress((void**)&hp, g_h);
    cudaGetSymbolAddress((void**)&aggp, g_agg);
    cudaGetSymbolAddress((void**)&h1p, g_h1);
    cudaGetSymbolAddress((void**)&statsp, g_stats);

    init_kernel<<<4096, 256>>>(x);

    // layer 0 (C_in = 32)
    edge_kernel<32><<<(EE + 63) / 64, 256>>>(x, eidx, ea, l0_ew, l0_eb, aggp);
    gemm_relu_kernel<32><<<(NN + 63) / 64, 256>>>(aggp, l0_w1, l0_b1, h1p);
    gemm_relu_kernel<64><<<(NN + 63) / 64, 256>>>(h1p, l0_w2, l0_b2, hp);
    bn_stats_kernel<<<512, 256>>>(hp, statsp);
    bn_apply_kernel<<<2048, 256>>>(hp, statsp, gam, bet, aggp);

    // layers 1..3 (C_in = 64)
    for (int i = 1; i < 4; i++) {
        edge_kernel<64><<<(EE + 31) / 32, 256>>>(hp, eidx, ea,
                                                 ew + (i - 1) * HH * 16, eb + (i - 1) * HH, aggp);
        gemm_relu_kernel<64><<<(NN + 63) / 64, 256>>>(aggp, w1 + (i - 1) * HH * HH,
                                                      b1 + (i - 1) * HH, h1p);
        gemm_relu_kernel<64><<<(NN + 63) / 64, 256>>>(h1p, w2 + (i - 1) * HH * HH,
                                                      b2 + (i - 1) * HH, hp);
        bn_stats_kernel<<<512, 256>>>(hp, statsp + i * 2 * HH);
        bn_apply_kernel<<<2048, 256>>>(hp, statsp + i * 2 * HH, gam + i * HH, bet + i * HH,
                                       (i < 3) ? aggp : nullptr);
    }

    pool_kernel<<<(NN * 4 + 255) / 256, 256>>>(hp, batch);
    head_kernel<<<GG, 128>>>(hw1, hb1, hw2, hb2, out);
}

// round 2
// speedup vs baseline: 1.1274x; 1.1274x over previous
#include <cuda_runtime.h>

#define NN 100000
#define EE 1600000
#define DIN_ 32
#define HH 64
#define GG 128
#define OUTC 10
#define NB_SCAN 98   // ceil(NN/1024)

typedef unsigned long long u64;

// ---------------- scratch (static device globals; no runtime alloc) ----------------
__device__ float g_h [(size_t)NN * HH];
__device__ float g_h1[(size_t)NN * HH];
__device__ float g_agg[(size_t)NN * HH];
__device__ float g_eas[(size_t)EE * 16];     // edge_attr permuted to CSR order
__device__ int   g_srcs[EE];                  // src permuted to CSR order
__device__ int   g_rowptr[NN + 1];
__device__ int   g_cur[NN];                   // degree, then cursor
__device__ int   g_bsum[128];
__device__ float g_stats[4 * 2 * HH];
__device__ float g_pool[GG * HH];
__device__ float g_cnt[GG];

// ---------------- f32x2 helpers (packed fp32 pairs; 2x FFMA issue rate path) -------
__device__ __forceinline__ u64 ffma2(u64 a, u64 b, u64 c) {
    u64 d; asm("fma.rn.f32x2 %0, %1, %2, %3;" : "=l"(d) : "l"(a), "l"(b), "l"(c)); return d;
}
__device__ __forceinline__ u64 fmul2(u64 a, u64 b) {
    u64 d; asm("mul.rn.f32x2 %0, %1, %2;" : "=l"(d) : "l"(a), "l"(b)); return d;
}
__device__ __forceinline__ void unpk2(u64 v, float& lo, float& hi) {
    asm("mov.b64 {%0, %1}, %2;" : "=f"(lo), "=f"(hi) : "l"(v));
}

// ---------------- init: zero deg/pool/cnt/stats ----------------
__global__ void init_kernel() {
    int i = blockIdx.x * blockDim.x + threadIdx.x;
    int stride = gridDim.x * blockDim.x;
    for (int idx = i; idx < NN; idx += stride) g_cur[idx] = 0;
    if (i < GG * HH) g_pool[i] = 0.f;
    if (i < GG) g_cnt[i] = 0.f;
    if (i < 4 * 2 * HH) g_stats[i] = 0.f;
}

// ---------------- CSR build ----------------
__global__ void hist_kernel(const int* __restrict__ eidx) {
    int e = blockIdx.x * blockDim.x + threadIdx.x;
    if (e < EE) atomicAdd(&g_cur[eidx[EE + e]], 1);
}

__global__ void __launch_bounds__(1024) scan_a_kernel() {
    int t = threadIdx.x, b = blockIdx.x;
    int i = b * 1024 + t;
    int v = (i < NN) ? g_cur[i] : 0;
    int lane = t & 31, wid = t >> 5;
    int inc = v;
#pragma unroll
    for (int d = 1; d < 32; d <<= 1) {
        int n = __shfl_up_sync(0xffffffffu, inc, d);
        if (lane >= d) inc += n;
    }
    __shared__ int wsum[32];
    if (lane == 31) wsum[wid] = inc;
    __syncthreads();
    if (wid == 0) {
        int wv = wsum[lane];
        int winc = wv;
#pragma unroll
        for (int d = 1; d < 32; d <<= 1) {
            int n = __shfl_up_sync(0xffffffffu, winc, d);
            if (lane >= d) winc += n;
        }
        wsum[lane] = winc - wv;           // exclusive warp offsets
        if (lane == 31) g_bsum[b] = winc; // block total
    }
    __syncthreads();
    if (i < NN) g_rowptr[i] = inc - v + wsum[wid];
}

__global__ void scan_b_kernel() {
    int t = threadIdx.x;             // 128 threads
    int v = (t < NB_SCAN) ? g_bsum[t] : 0;
    int lane = t & 31, wid = t >> 5;
    int inc = v;
#pragma unroll
    for (int d = 1; d < 32; d <<= 1) {
        int n = __shfl_up_sync(0xffffffffu, inc, d);
        if (lane >= d) inc += n;
    }
    __shared__ int wsum[4];
    if (lane == 31) wsum[wid] = inc;
    __syncthreads();
    int woff = 0;
    for (int w = 0; w < wid; w++) woff += wsum[w];
    if (t < NB_SCAN) g_bsum[t] = inc - v + woff;
}

__global__ void scan_c_kernel() {
    int i = blockIdx.x * blockDim.x + threadIdx.x;
    if (i < NN) {
        int r = g_rowptr[i] + g_bsum[i >> 10];
        g_rowptr[i] = r;
        g_cur[i] = r;
    }
    if (i == 0) g_rowptr[NN] = EE;
}

__global__ void scatter_kernel(const int* __restrict__ eidx, const float* __restrict__ ea) {
    int e = blockIdx.x * blockDim.x + threadIdx.x;
    if (e >= EE) return;
    int d = eidx[EE + e];
    int pos = atomicAdd(&g_cur[d], 1);
    g_srcs[pos] = eidx[e];
    const float4* s4 = (const float4*)(ea + (size_t)e * 16);
    float4* d4 = (float4*)(g_eas + (size_t)pos * 16);
    d4[0] = s4[0]; d4[1] = s4[1]; d4[2] = s4[2]; d4[3] = s4[3];
}

// ---------------- aggregation: agg[n] = x[n] + sum_e relu(x[src]+ea@ew^T+eb) -------
// warp per node; no atomics. C=64: lane owns channel pair (2l, 2l+1).
__global__ void __launch_bounds__(256) agg64_kernel(
    const float* __restrict__ xin, const float* __restrict__ ew,
    const float* __restrict__ ebv, float* __restrict__ agg)
{
    int warp = blockIdx.x * 8 + (threadIdx.x >> 5);
    if (warp >= NN) return;
    int lane = threadIdx.x & 31;
    int c0 = lane * 2;

    u64 W0[8], W1[8];
    const ulonglong2* w0p = (const ulonglong2*)(ew + c0 * 16);
    const ulonglong2* w1p = (const ulonglong2*)(ew + c0 * 16 + 16);
#pragma unroll
    for (int q = 0; q < 4; q++) {
        ulonglong2 t0 = w0p[q]; W0[2 * q] = t0.x; W0[2 * q + 1] = t0.y;
        ulonglong2 t1 = w1p[q]; W1[2 * q] = t1.x; W1[2 * q + 1] = t1.y;
    }
    float eb0 = ebv[c0], eb1 = ebv[c0 + 1];
    int start = g_rowptr[warp], end = g_rowptr[warp + 1];
    float A0 = 0.f, A1 = 0.f;

#pragma unroll 2
    for (int j = start; j < end; j++) {
        int s = g_srcs[j];                                        // warp-broadcast
        float2 xs = *(const float2*)(xin + (size_t)s * 64 + c0);
        const ulonglong2* ap = (const ulonglong2*)(g_eas + (size_t)j * 16);
        ulonglong2 q0 = ap[0], q1 = ap[1], q2 = ap[2], q3 = ap[3]; // warp-broadcast
        u64 P[8] = {q0.x, q0.y, q1.x, q1.y, q2.x, q2.y, q3.x, q3.y};
        u64 acc0 = fmul2(P[0], W0[0]);
        u64 acc1 = fmul2(P[0], W1[0]);
#pragma unroll
        for (int k = 1; k < 8; k++) {
            acc0 = ffma2(P[k], W0[k], acc0);
            acc1 = ffma2(P[k], W1[k], acc1);
        }
        float l0, h0, l1, h1;
        unpk2(acc0, l0, h0); unpk2(acc1, l1, h1);
        A0 += fmaxf(xs.x + eb0 + l0 + h0, 0.f);
        A1 += fmaxf(xs.y + eb1 + l1 + h1, 0.f);
    }
    float2 xn = *(const float2*)(xin + (size_t)warp * 64 + c0);
    float2 o; o.x = xn.x + A0; o.y = xn.y + A1;
    *(float2*)(agg + (size_t)warp * 64 + c0) = o;
}

// C=32 (layer 0): lane owns one channel.
__global__ void __launch_bounds__(256) agg32_kernel(
    const float* __restrict__ xin, const float* __restrict__ ew,
    const float* __restrict__ ebv, float* __restrict__ agg)
{
    int warp = blockIdx.x * 8 + (threadIdx.x >> 5);
    if (warp >= NN) return;
    int lane = threadIdx.x & 31;

    u64 W[8];
    const ulonglong2* wp = (const ulonglong2*)(ew + lane * 16);
#pragma unroll
    for (int q = 0; q < 4; q++) { ulonglong2 t = wp[q]; W[2 * q] = t.x; W[2 * q + 1] = t.y; }
    float eb = ebv[lane];
    int start = g_rowptr[warp], end = g_rowptr[warp + 1];
    float A = 0.f;

#pragma unroll 2
    for (int j = start; j < end; j++) {
        int s = g_srcs[j];
        float xs = xin[(size_t)s * 32 + lane];
        const ulonglong2* ap = (const ulonglong2*)(g_eas + (size_t)j * 16);
        ulonglong2 q0 = ap[0], q1 = ap[1], q2 = ap[2], q3 = ap[3];
        u64 P[8] = {q0.x, q0.y, q1.x, q1.y, q2.x, q2.y, q3.x, q3.y};
        u64 acc = fmul2(P[0], W[0]);
#pragma unroll
        for (int k = 1; k < 8; k++) acc = ffma2(P[k], W[k], acc);
        float lo, hi; unpk2(acc, lo, hi);
        A += fmaxf(xs + eb + lo + hi, 0.f);
    }
    agg[(size_t)warp * 32 + lane] = xin[(size_t)warp * 32 + lane] + A;
}

// ---------------- node GEMM (f32x2): out = relu(in @ w^T + b), 64 out channels ----
template <int K>
__global__ void __launch_bounds__(256) gemm_relu_kernel(
    const float* __restrict__ in, const float* __restrict__ w,
    const float* __restrict__ bias, float* __restrict__ out)
{
    __shared__ __align__(16) float in_s[64][K + 4];
    __shared__ __align__(16) float w_s[64][K + 4];
    constexpr int K4 = K / 4;
    int t = threadIdx.x;
    int n0 = blockIdx.x * 64;

    for (int i = t; i < 64 * K4; i += 256) {
        int r = i / K4, c4 = i % K4;
        *(float4*)&w_s[r][c4 * 4] = ((const float4*)w)[i];
        int n = n0 + r;
        float4 v = (n < NN) ? ((const float4*)in)[(size_t)n * K4 + c4] : make_float4(0.f, 0.f, 0.f, 0.f);
        *(float4*)&in_s[r][c4 * 4] = v;
    }
    __syncthreads();

    int tx = t & 15, ty = t >> 4;
    u64 acc2[4][4] = {};
#pragma unroll
    for (int k = 0; k < K; k += 4) {
        ulonglong2 a[4], b[4];
#pragma unroll
        for (int i = 0; i < 4; i++) a[i] = *(const ulonglong2*)&in_s[ty * 4 + i][k];
#pragma unroll
        for (int j = 0; j < 4; j++) b[j] = *(const ulonglong2*)&w_s[tx + j * 16][k];
#pragma unroll
        for (int i = 0; i < 4; i++)
#pragma unroll
            for (int j = 0; j < 4; j++)
                acc2[i][j] = ffma2(a[i].x, b[j].x, ffma2(a[i].y, b[j].y, acc2[i][j]));
    }
#pragma unroll
    for (int j = 0; j < 4; j++) {
        int c = tx + j * 16;
        float bb = bias[c];
#pragma unroll
        for (int i = 0; i < 4; i++) {
            int n = n0 + ty * 4 + i;
            if (n < NN) {
                float lo, hi; unpk2(acc2[i][j], lo, hi);
                out[(size_t)n * 64 + c] = fmaxf(lo + hi + bb, 0.f);
            }
        }
    }
}

// ---------------- BN stats ----------------
__global__ void bn_stats_kernel(const float* __restrict__ h, float* __restrict__ stats) {
    int t = threadIdx.x;
    int c = t & 63, r = t >> 6;
    float s = 0.f, q = 0.f;
    for (int n = blockIdx.x * 4 + r; n < NN; n += gridDim.x * 4) {
        float v = h[(size_t)n * 64 + c];
        s += v; q = fmaf(v, v, q);
    }
    __shared__ float sh[256], qh[256];
    sh[t] = s; qh[t] = q;
    __syncthreads();
    if (t < 64) {
        atomicAdd(&stats[t],      sh[t] + sh[t + 64] + sh[t + 128] + sh[t + 192]);
        atomicAdd(&stats[64 + t], qh[t] + qh[t + 64] + qh[t + 128] + qh[t + 192]);
    }
}

// ---------------- BN apply + relu (vectorized) ----------------
__global__ void bn_apply_kernel(float* __restrict__ h, const float* __restrict__ stats,
                                const float* __restrict__ gamma, const float* __restrict__ beta) {
    __shared__ float sc[64], sf[64];
    int t = threadIdx.x;
    if (t < 64) {
        float mu = stats[t] * (1.0f / NN);
        float var = stats[64 + t] * (1.0f / NN) - mu * mu;
        float inv = rsqrtf(var + 1e-5f);
        float g = gamma[t], b = beta[t];
        sc[t] = inv * g;
        sf[t] = b - mu * inv * g;
    }
    __syncthreads();
    int i0 = blockIdx.x * blockDim.x + t;
    float4* h4 = (float4*)h;
    for (int i = i0; i < NN * 16; i += gridDim.x * blockDim.x) {
        int c0 = (i & 15) * 4;
        float4 v = h4[i];
        v.x = fmaxf(fmaf(v.x, sc[c0 + 0], sf[c0 + 0]), 0.f);
        v.y = fmaxf(fmaf(v.y, sc[c0 + 1], sf[c0 + 1]), 0.f);
        v.z = fmaxf(fmaf(v.z, sc[c0 + 2], sf[c0 + 2]), 0.f);
        v.w = fmaxf(fmaf(v.w, sc[c0 + 3], sf[c0 + 3]), 0.f);
        h4[i] = v;
    }
}

// ---------------- pool: batch is sorted; warp accumulates runs, flushes on change --
__global__ void pool_kernel(const float* __restrict__ h, const int* __restrict__ batch) {
    int warp = blockIdx.x * (blockDim.x >> 5) + (threadIdx.x >> 5);
    int lane = threadIdx.x & 31;
    int base = warp * 32;
    if (base >= NN) return;
    int end = min(base + 32, NN);
    int c0 = lane * 2;

    int curb = batch[base];
    float a0 = 0.f, a1 = 0.f, cf = 0.f;
    for (int n = base; n < end; n++) {
        int b = batch[n];                         // warp-broadcast
        if (b != curb) {
            atomicAdd(&g_pool[curb * 64 + c0], a0);
            atomicAdd(&g_pool[curb * 64 + c0 + 1], a1);
            if (lane == 0) atomicAdd(&g_cnt[curb], cf);
            a0 = a1 = cf = 0.f;
            curb = b;
        }
        float2 v = *(const float2*)(h + (size_t)n * 64 + c0);
        a0 += v.x; a1 += v.y; cf += 1.f;
    }
    atomicAdd(&g_pool[curb * 64 + c0], a0);
    atomicAdd(&g_pool[curb * 64 + c0 + 1], a1);
    if (lane == 0) atomicAdd(&g_cnt[curb], cf);
}

// ---------------- MLP head ----------------
__global__ void head_kernel(const float* __restrict__ hw1, const float* __restrict__ hb1,
                            const float* __restrict__ hw2, const float* __restrict__ hb2,
                            float* __restrict__ out) {
    int g = blockIdx.x, t = threadIdx.x;
    __shared__ float p[64];
    __shared__ float z[128];
    if (t < 64) {
        float c = g_cnt[g];
        p[t] = g_pool[g * 64 + t] / fmaxf(c, 1.0f);
    }
    __syncthreads();
    float s = hb1[t];
#pragma unroll 8
    for (int k = 0; k < 64; k++) s = fmaf(p[k], hw1[t * 64 + k], s);
    z[t] = fmaxf(s, 0.f);
    __syncthreads();
    if (t < OUTC) {
        float s2 = hb2[t];
#pragma unroll 8
        for (int k = 0; k < 128; k++) s2 = fmaf(z[k], hw2[t * 128 + k], s2);
        out[g * OUTC + t] = s2;
    }
}

// ---------------- launch ----------------
extern "C" void kernel_launch(void* const* d_in, const int* in_sizes, int n_in,
                              void* d_out, int out_size) {
    const float* x     = (const float*)d_in[0];
    const int*   eidx  = (const int*)  d_in[1];
    const float* ea    = (const float*)d_in[2];
    const int*   batch = (const int*)  d_in[3];
    const float* l0_ew = (const float*)d_in[4];
    const float* l0_eb = (const float*)d_in[5];
    const float* l0_w1 = (const float*)d_in[6];
    const float* l0_b1 = (const float*)d_in[7];
    const float* l0_w2 = (const float*)d_in[8];
    const float* l0_b2 = (const float*)d_in[9];
    const float* ew    = (const float*)d_in[10];
    const float* eb    = (const float*)d_in[11];
    const float* w1    = (const float*)d_in[12];
    const float* b1    = (const float*)d_in[13];
    const float* w2    = (const float*)d_in[14];
    const float* b2    = (const float*)d_in[15];
    const float* gam   = (const float*)d_in[16];
    const float* bet   = (const float*)d_in[17];
    const float* hw1   = (const float*)d_in[18];
    const float* hb1   = (const float*)d_in[19];
    const float* hw2   = (const float*)d_in[20];
    const float* hb2   = (const float*)d_in[21];
    float* out = (float*)d_out;

    float *hp, *h1p, *aggp, *statsp;
    cudaGetSymbolAddress((void**)&hp, g_h);
    cudaGetSymbolAddress((void**)&h1p, g_h1);
    cudaGetSymbolAddress((void**)&aggp, g_agg);
    cudaGetSymbolAddress((void**)&statsp, g_stats);

    // CSR build (once per launch)
    init_kernel<<<512, 256>>>();
    hist_kernel<<<(EE + 255) / 256, 256>>>(eidx);
    scan_a_kernel<<<NB_SCAN, 1024>>>();
    scan_b_kernel<<<1, 128>>>();
    scan_c_kernel<<<(NN + 255) / 256, 256>>>();
    scatter_kernel<<<(EE + 255) / 256, 256>>>(eidx, ea);

    int agg_blocks = (NN * 32 + 255) / 256;

    // layer 0 (C_in = 32)
    agg32_kernel<<<agg_blocks, 256>>>(x, l0_ew, l0_eb, aggp);
    gemm_relu_kernel<32><<<(NN + 63) / 64, 256>>>(aggp, l0_w1, l0_b1, h1p);
    gemm_relu_kernel<64><<<(NN + 63) / 64, 256>>>(h1p, l0_w2, l0_b2, hp);
    bn_stats_kernel<<<512, 256>>>(hp, statsp);
    bn_apply_kernel<<<2048, 256>>>(hp, statsp, gam, bet);

    // layers 1..3 (C_in = 64)
    for (int i = 1; i < 4; i++) {
        agg64_kernel<<<agg_blocks, 256>>>(hp, ew + (i - 1) * HH * 16, eb + (i - 1) * HH, aggp);
        gemm_relu_kernel<64><<<(NN + 63) / 64, 256>>>(aggp, w1 + (i - 1) * HH * HH,
                                                      b1 + (i - 1) * HH, h1p);
        gemm_relu_kernel<64><<<(NN + 63) / 64, 256>>>(h1p, w2 + (i - 1) * HH * HH,
                                                      b2 + (i - 1) * HH, hp);
        bn_stats_kernel<<<512, 256>>>(hp, statsp + i * 2 * HH);
        bn_apply_kernel<<<2048, 256>>>(hp, statsp + i * 2 * HH, gam + i * HH, bet + i * HH);
    }

    pool_kernel<<<(NN / 32 + 7) / 8, 256>>>(hp, batch);
    head_kernel<<<GG, 128>>>(hw1, hb1, hw2, hb2, out);
}

// round 3
// speedup vs baseline: 1.1713x; 1.0389x over previous
#include <cuda_runtime.h>

#define NN 100000
#define EE 1600000
#define DIN_ 32
#define HH 64
#define GG 128
#define OUTC 10

typedef unsigned long long u64;

// ---------------- scratch (static device globals; no runtime alloc) ----------------
__device__ float g_h [(size_t)NN * HH];       // layer output (pre-BN "hraw")
__device__ float g_agg[(size_t)NN * HH];      // aggregation result
__device__ float g_eas[(size_t)EE * 16];      // edge_attr permuted to CSR order
__device__ int   g_srcs[EE];                  // src permuted to CSR order
__device__ int   g_rowptr[NN + 1];
__device__ int   g_cur[NN];                   // degree, then cursor
__device__ float g_stats[4 * 2 * HH];         // per-layer BN sum / sumsq
__device__ float g_bnsc[4 * HH];              // BN scale  (gamma*inv)
__device__ float g_bnsf[4 * HH];              // BN shift  (beta - mu*gamma*inv)
__device__ float g_pool[GG * HH];
__device__ float g_cnt[GG];

// ---------------- f32x2 helpers ----------------
__device__ __forceinline__ u64 ffma2(u64 a, u64 b, u64 c) {
    u64 d; asm("fma.rn.f32x2 %0, %1, %2, %3;" : "=l"(d) : "l"(a), "l"(b), "l"(c)); return d;
}
__device__ __forceinline__ u64 fmul2(u64 a, u64 b) {
    u64 d; asm("mul.rn.f32x2 %0, %1, %2;" : "=l"(d) : "l"(a), "l"(b)); return d;
}
__device__ __forceinline__ void unpk2(u64 v, float& lo, float& hi) {
    asm("mov.b64 {%0, %1}, %2;" : "=f"(lo), "=f"(hi) : "l"(v));
}

// ---------------- CSR build ----------------
__global__ void hist_kernel(const int* __restrict__ eidx) {
    int e = blockIdx.x * blockDim.x + threadIdx.x;
    if (e < EE) atomicAdd(&g_cur[eidx[EE + e]], 1);
}

// single-block exclusive scan of g_cur[0..NN) -> g_rowptr, g_cur (cursor copy)
__global__ void __launch_bounds__(1024) scan_kernel() {
    int t = threadIdx.x;
    int sum = 0;
    if (t < 1000) {
        const int4* p = (const int4*)(g_cur + t * 100);
#pragma unroll 5
        for (int q = 0; q < 25; q++) { int4 v = p[q]; sum += v.x + v.y + v.z + v.w; }
    }
    int lane = t & 31, wid = t >> 5;
    int inc = sum;
#pragma unroll
    for (int d = 1; d < 32; d <<= 1) {
        int n = __shfl_up_sync(0xffffffffu, inc, d);
        if (lane >= d) inc += n;
    }
    __shared__ int wsum[32];
    if (lane == 31) wsum[wid] = inc;
    __syncthreads();
    if (wid == 0) {
        int wv = wsum[lane];
        int winc = wv;
#pragma unroll
        for (int d = 1; d < 32; d <<= 1) {
            int n = __shfl_up_sync(0xffffffffu, winc, d);
            if (lane >= d) winc += n;
        }
        wsum[lane] = winc - wv;
    }
    __syncthreads();
    if (t < 1000) {
        int run = inc - sum + wsum[wid];   // exclusive prefix at t*100
        const int4* p = (const int4*)(g_cur + t * 100);
#pragma unroll 5
        for (int q = 0; q < 25; q++) {
            int4 v = p[q];
            int i = t * 100 + q * 4;
            int4 r; r.x = run; run += v.x; r.y = run; run += v.y;
            r.z = run; run += v.z; r.w = run; run += v.w;
            *(int4*)(g_rowptr + i) = r;
            *(int4*)(g_cur + i) = r;
        }
    }
    if (t == 1023) g_rowptr[NN] = EE;
}

__global__ void scatter_kernel(const int* __restrict__ eidx, const float* __restrict__ ea) {
    int e = blockIdx.x * blockDim.x + threadIdx.x;
    if (e >= EE) return;
    int d = eidx[EE + e];
    int pos = atomicAdd(&g_cur[d], 1);
    g_srcs[pos] = eidx[e];
    const float4* s4 = (const float4*)(ea + (size_t)e * 16);
    float4* d4 = (float4*)(g_eas + (size_t)pos * 16);
    d4[0] = s4[0]; d4[1] = s4[1]; d4[2] = s4[2]; d4[3] = s4[3];
}

// ---------------- layer-0 aggregation (C=32, raw x, pipelined) ----------------
__global__ void __launch_bounds__(128) agg32_kernel(
    const float* __restrict__ xin, const float* __restrict__ ew,
    const float* __restrict__ ebv, float* __restrict__ agg)
{
    int warp = blockIdx.x * 4 + (threadIdx.x >> 5);
    if (warp >= NN) return;
    int lane = threadIdx.x & 31;

    u64 W[8];
    {
        const ulonglong2* wp = (const ulonglong2*)(ew + lane * 16);
#pragma unroll
        for (int q = 0; q < 4; q++) { ulonglong2 v = wp[q]; W[2*q] = v.x; W[2*q+1] = v.y; }
    }
    float eb = ebv[lane];
    int start = g_rowptr[warp];
    int n = g_rowptr[warp + 1] - start;
    float A = 0.f;

    if (n > 0) {
        const int* sp = g_srcs + start;
        int s_nxt = (n > 1) ? sp[1] : 0;
        float xs = xin[(size_t)sp[0] * 32 + lane];
        u64 P[8];
        {
            const ulonglong2* ap = (const ulonglong2*)(g_eas + (size_t)start * 16);
#pragma unroll
            for (int q = 0; q < 4; q++) { ulonglong2 v = ap[q]; P[2*q] = v.x; P[2*q+1] = v.y; }
        }
#pragma unroll 2
        for (int j = 0; j < n; j++) {
            int s_nn = (j + 2 < n) ? sp[j + 2] : 0;
            float xs_n = 0.f;
            u64 Q[8] = {};
            if (j + 1 < n) {
                xs_n = xin[(size_t)s_nxt * 32 + lane];
                const ulonglong2* aq = (const ulonglong2*)(g_eas + (size_t)(start + j + 1) * 16);
#pragma unroll
                for (int q = 0; q < 4; q++) { ulonglong2 v = aq[q]; Q[2*q] = v.x; Q[2*q+1] = v.y; }
            }
            u64 acc = fmul2(P[0], W[0]);
#pragma unroll
            for (int k = 1; k < 8; k++) acc = ffma2(P[k], W[k], acc);
            float lo, hi; unpk2(acc, lo, hi);
            A += fmaxf(xs + eb + lo + hi, 0.f);
            s_nxt = s_nn; xs = xs_n;
#pragma unroll
            for (int k = 0; k < 8; k++) P[k] = Q[k];
        }
    }
    agg[(size_t)warp * 32 + lane] = xin[(size_t)warp * 32 + lane] + A;
}

// ---------------- layers 1-3 aggregation (C=64, BN+relu folded into gather) -------
__global__ void __launch_bounds__(128) agg64_kernel(
    const float* __restrict__ hraw, const float* __restrict__ ew,
    const float* __restrict__ ebv, const float* __restrict__ bnsc,
    const float* __restrict__ bnsf, float* __restrict__ agg)
{
    int warp = blockIdx.x * 4 + (threadIdx.x >> 5);
    if (warp >= NN) return;
    int lane = threadIdx.x & 31;
    int c0 = lane * 2;

    u64 W0[8], W1[8];
    {
        const ulonglong2* w0p = (const ulonglong2*)(ew + c0 * 16);
        const ulonglong2* w1p = (const ulonglong2*)(ew + c0 * 16 + 16);
#pragma unroll
        for (int q = 0; q < 4; q++) {
            ulonglong2 v0 = w0p[q]; W0[2*q] = v0.x; W0[2*q+1] = v0.y;
            ulonglong2 v1 = w1p[q]; W1[2*q] = v1.x; W1[2*q+1] = v1.y;
        }
    }
    float eb0 = ebv[c0], eb1 = ebv[c0 + 1];
    float sc0 = bnsc[c0], sc1 = bnsc[c0 + 1];
    float sf0 = bnsf[c0], sf1 = bnsf[c0 + 1];
    int start = g_rowptr[warp];
    int n = g_rowptr[warp + 1] - start;
    float A0 = 0.f, A1 = 0.f;

    if (n > 0) {
        const int* sp = g_srcs + start;
        int s_nxt = (n > 1) ? sp[1] : 0;
        float2 xs = *(const float2*)(hraw + (size_t)sp[0] * 64 + c0);
        u64 P[8];
        {
            const ulonglong2* ap = (const ulonglong2*)(g_eas + (size_t)start * 16);
#pragma unroll
            for (int q = 0; q < 4; q++) { ulonglong2 v = ap[q]; P[2*q] = v.x; P[2*q+1] = v.y; }
        }
#pragma unroll 2
        for (int j = 0; j < n; j++) {
            int s_nn = (j + 2 < n) ? sp[j + 2] : 0;
            float2 xs_n = make_float2(0.f, 0.f);
            u64 Q[8] = {};
            if (j + 1 < n) {
                xs_n = *(const float2*)(hraw + (size_t)s_nxt * 64 + c0);
                const ulonglong2* aq = (const ulonglong2*)(g_eas + (size_t)(start + j + 1) * 16);
#pragma unroll
                for (int q = 0; q < 4; q++) { ulonglong2 v = aq[q]; Q[2*q] = v.x; Q[2*q+1] = v.y; }
            }
            u64 acc0 = fmul2(P[0], W0[0]);
            u64 acc1 = fmul2(P[0], W1[0]);
#pragma unroll
            for (int k = 1; k < 8; k++) {
                acc0 = ffma2(P[k], W0[k], acc0);
                acc1 = ffma2(P[k], W1[k], acc1);
            }
            float l0, h0, l1, h1;
            unpk2(acc0, l0, h0); unpk2(acc1, l1, h1);
            float x0 = fmaxf(fmaf(xs.x, sc0, sf0), 0.f);   // BN+relu fold
            float x1 = fmaxf(fmaf(xs.y, sc1, sf1), 0.f);
            A0 += fmaxf(x0 + eb0 + l0 + h0, 0.f);
            A1 += fmaxf(x1 + eb1 + l1 + h1, 0.f);
            s_nxt = s_nn; xs = xs_n;
#pragma unroll
            for (int k = 0; k < 8; k++) P[k] = Q[k];
        }
    }
    float2 xn = *(const float2*)(hraw + (size_t)warp * 64 + c0);
    float2 o;
    o.x = fmaxf(fmaf(xn.x, sc0, sf0), 0.f) + A0;
    o.y = fmaxf(fmaf(xn.y, sc1, sf1), 0.f) + A1;
    *(float2*)(agg + (size_t)warp * 64 + c0) = o;
}

// ---------------- fused node MLP: out = relu(relu(in@w1^T+b1)@w2^T+b2) + BN stats --
template <int K>
__global__ void __launch_bounds__(256) gemm_fused_kernel(
    const float* __restrict__ in, const float* __restrict__ w1,
    const float* __restrict__ b1, const float* __restrict__ w2,
    const float* __restrict__ b2, float* __restrict__ out,
    float* __restrict__ stats)
{
    __shared__ __align__(16) float a_s[64][K + 4];
    __shared__ __align__(16) float w_s[64][68];
    __shared__ __align__(16) float h_s[64][68];
    constexpr int K4 = K / 4;
    int t = threadIdx.x;
    int n0 = blockIdx.x * 64;
    int tx = t & 15, ty = t >> 4;

    for (int i = t; i < 64 * K4; i += 256) {
        int r = i / K4, c4 = i % K4;
        *(float4*)&w_s[r][c4 * 4] = ((const float4*)w1)[i];
        int n = n0 + r;
        float4 v = (n < NN) ? ((const float4*)in)[(size_t)n * K4 + c4] : make_float4(0.f,0.f,0.f,0.f);
        *(float4*)&a_s[r][c4 * 4] = v;
    }
    __syncthreads();

    // GEMM1 -> h_s (relu + bias)
    {
        u64 acc2[4][4] = {};
#pragma unroll
        for (int k = 0; k < K; k += 4) {
            ulonglong2 a[4], b[4];
#pragma unroll
            for (int i = 0; i < 4; i++) a[i] = *(const ulonglong2*)&a_s[ty * 4 + i][k];
#pragma unroll
            for (int j = 0; j < 4; j++) b[j] = *(const ulonglong2*)&w_s[tx + j * 16][k];
#pragma unroll
            for (int i = 0; i < 4; i++)
#pragma unroll
                for (int j = 0; j < 4; j++)
                    acc2[i][j] = ffma2(a[i].x, b[j].x, ffma2(a[i].y, b[j].y, acc2[i][j]));
        }
#pragma unroll
        for (int j = 0; j < 4; j++) {
            int c = tx + j * 16;
            float bb = b1[c];
#pragma unroll
            for (int i = 0; i < 4; i++) {
                float lo, hi; unpk2(acc2[i][j], lo, hi);
                h_s[ty * 4 + i][c] = fmaxf(lo + hi + bb, 0.f);
            }
        }
    }
    __syncthreads();
    for (int i = t; i < 64 * 16; i += 256) {
        int r = i >> 4, c4 = i & 15;
        *(float4*)&w_s[r][c4 * 4] = ((const float4*)w2)[i];
    }
    __syncthreads();

    // GEMM2
    float val[4][4];
    {
        u64 acc2[4][4] = {};
#pragma unroll
        for (int k = 0; k < 64; k += 4) {
            ulonglong2 a[4], b[4];
#pragma unroll
            for (int i = 0; i < 4; i++) a[i] = *(const ulonglong2*)&h_s[ty * 4 + i][k];
#pragma unroll
            for (int j = 0; j < 4; j++) b[j] = *(const ulonglong2*)&w_s[tx + j * 16][k];
#pragma unroll
            for (int i = 0; i < 4; i++)
#pragma unroll
                for (int j = 0; j < 4; j++)
                    acc2[i][j] = ffma2(a[i].x, b[j].x, ffma2(a[i].y, b[j].y, acc2[i][j]));
        }
#pragma unroll
        for (int j = 0; j < 4; j++) {
            int c = tx + j * 16;
            float bb = b2[c];
#pragma unroll
            for (int i = 0; i < 4; i++) {
                float lo, hi; unpk2(acc2[i][j], lo, hi);
                val[i][j] = fmaxf(lo + hi + bb, 0.f);
            }
        }
    }
    __syncthreads();   // all smem reads done; reuse a_s/h_s for reductions

    float* redS = &a_s[0][0];
    float* redQ = &h_s[0][0];
#pragma unroll
    for (int j = 0; j < 4; j++) {
        int c = tx + j * 16;
        float s = 0.f, q = 0.f;
#pragma unroll
        for (int i = 0; i < 4; i++) {
            int n = n0 + ty * 4 + i;
            if (n < NN) {
                float v = val[i][j];
                out[(size_t)n * 64 + c] = v;
                s += v; q = fmaf(v, v, q);
            }
        }
        redS[ty * 64 + c] = s;
        redQ[ty * 64 + c] = q;
    }
    __syncthreads();
    if (t < 64) {
        float S = 0.f, Q = 0.f;
#pragma unroll
        for (int r = 0; r < 16; r++) { S += redS[r * 64 + t]; Q += redQ[r * 64 + t]; }
        atomicAdd(&stats[t], S);
        atomicAdd(&stats[64 + t], Q);
    }
}

// ---------------- BN coefficients ----------------
__global__ void bn_coef_kernel(const float* __restrict__ stats,
                               const float* __restrict__ gamma, const float* __restrict__ beta,
                               float* __restrict__ sc, float* __restrict__ sf) {
    int t = threadIdx.x;
    float mu = stats[t] * (1.0f / NN);
    float var = stats[64 + t] * (1.0f / NN) - mu * mu;
    float inv = rsqrtf(var + 1e-5f);
    float g = gamma[t], b = beta[t];
    sc[t] = inv * g;
    sf[t] = b - mu * inv * g;
}

// ---------------- pool (BN of last layer folded; batch sorted) ----------------
__global__ void pool_kernel(const float* __restrict__ hraw, const int* __restrict__ batch,
                            const float* __restrict__ bnsc, const float* __restrict__ bnsf) {
    int warp = blockIdx.x * (blockDim.x >> 5) + (threadIdx.x >> 5);
    int lane = threadIdx.x & 31;
    int base = warp * 32;
    if (base >= NN) return;
    int end = min(base + 32, NN);
    int c0 = lane * 2;
    float sc0 = bnsc[c0], sc1 = bnsc[c0 + 1];
    float sf0 = bnsf[c0], sf1 = bnsf[c0 + 1];

    int curb = batch[base];
    float a0 = 0.f, a1 = 0.f, cf = 0.f;
    for (int n = base; n < end; n++) {
        int b = batch[n];
        if (b != curb) {
            atomicAdd(&g_pool[curb * 64 + c0], a0);
            atomicAdd(&g_pool[curb * 64 + c0 + 1], a1);
            if (lane == 0) atomicAdd(&g_cnt[curb], cf);
            a0 = a1 = cf = 0.f;
            curb = b;
        }
        float2 v = *(const float2*)(hraw + (size_t)n * 64 + c0);
        a0 += fmaxf(fmaf(v.x, sc0, sf0), 0.f);
        a1 += fmaxf(fmaf(v.y, sc1, sf1), 0.f);
        cf += 1.f;
    }
    atomicAdd(&g_pool[curb * 64 + c0], a0);
    atomicAdd(&g_pool[curb * 64 + c0 + 1], a1);
    if (lane == 0) atomicAdd(&g_cnt[curb], cf);
}

// ---------------- MLP head ----------------
__global__ void head_kernel(const float* __restrict__ hw1, const float* __restrict__ hb1,
                            const float* __restrict__ hw2, const float* __restrict__ hb2,
                            float* __restrict__ out) {
    int g = blockIdx.x, t = threadIdx.x;
    __shared__ float p[64];
    __shared__ float z[128];
    if (t < 64) {
        float c = g_cnt[g];
        p[t] = g_pool[g * 64 + t] / fmaxf(c, 1.0f);
    }
    __syncthreads();
    float s = hb1[t];
#pragma unroll 8
    for (int k = 0; k < 64; k++) s = fmaf(p[k], hw1[t * 64 + k], s);
    z[t] = fmaxf(s, 0.f);
    __syncthreads();
    if (t < OUTC) {
        float s2 = hb2[t];
#pragma unroll 8
        for (int k = 0; k < 128; k++) s2 = fmaf(z[k], hw2[t * 128 + k], s2);
        out[g * OUTC + t] = s2;
    }
}

// ---------------- launch ----------------
extern "C" void kernel_launch(void* const* d_in, const int* in_sizes, int n_in,
                              void* d_out, int out_size) {
    const float* x     = (const float*)d_in[0];
    const int*   eidx  = (const int*)  d_in[1];
    const float* ea    = (const float*)d_in[2];
    const int*   batch = (const int*)  d_in[3];
    const float* l0_ew = (const float*)d_in[4];
    const float* l0_eb = (const float*)d_in[5];
    const float* l0_w1 = (const float*)d_in[6];
    const float* l0_b1 = (const float*)d_in[7];
    const float* l0_w2 = (const float*)d_in[8];
    const float* l0_b2 = (const float*)d_in[9];
    const float* ew    = (const float*)d_in[10];
    const float* eb    = (const float*)d_in[11];
    const float* w1    = (const float*)d_in[12];
    const float* b1    = (const float*)d_in[13];
    const float* w2    = (const float*)d_in[14];
    const float* b2    = (const float*)d_in[15];
    const float* gam   = (const float*)d_in[16];
    const float* bet   = (const float*)d_in[17];
    const float* hw1   = (const float*)d_in[18];
    const float* hb1   = (const float*)d_in[19];
    const float* hw2   = (const float*)d_in[20];
    const float* hb2   = (const float*)d_in[21];
    float* out = (float*)d_out;

    float *hp, *aggp, *statsp, *scp, *sfp, *poolp, *cntp;
    int *curp;
    cudaGetSymbolAddress((void**)&hp, g_h);
    cudaGetSymbolAddress((void**)&aggp, g_agg);
    cudaGetSymbolAddress((void**)&statsp, g_stats);
    cudaGetSymbolAddress((void**)&scp, g_bnsc);
    cudaGetSymbolAddress((void**)&sfp, g_bnsf);
    cudaGetSymbolAddress((void**)&poolp, g_pool);
    cudaGetSymbolAddress((void**)&cntp, g_cnt);
    cudaGetSymbolAddress((void**)&curp, g_cur);

    cudaMemsetAsync(curp, 0, NN * sizeof(int));
    cudaMemsetAsync(statsp, 0, 4 * 2 * HH * sizeof(float));
    cudaMemsetAsync(poolp, 0, GG * HH * sizeof(float));
    cudaMemsetAsync(cntp, 0, GG * sizeof(float));

    // CSR build
    hist_kernel<<<(EE + 255) / 256, 256>>>(eidx);
    scan_kernel<<<1, 1024>>>();
    scatter_kernel<<<(EE + 255) / 256, 256>>>(eidx, ea);

    int agg_blocks = (NN + 3) / 4;

    // layer 0
    agg32_kernel<<<agg_blocks, 128>>>(x, l0_ew, l0_eb, aggp);
    gemm_fused_kernel<32><<<(NN + 63) / 64, 256>>>(aggp, l0_w1, l0_b1, l0_w2, l0_b2, hp, statsp);
    bn_coef_kernel<<<1, 64>>>(statsp, gam, bet, scp, sfp);

    // layers 1..3
    for (int i = 1; i < 4; i++) {
        agg64_kernel<<<agg_blocks, 128>>>(hp, ew + (i - 1) * HH * 16, eb + (i - 1) * HH,
                                          scp + (i - 1) * HH, sfp + (i - 1) * HH, aggp);
        gemm_fused_kernel<64><<<(NN + 63) / 64, 256>>>(aggp, w1 + (i - 1) * HH * HH,
                                                       b1 + (i - 1) * HH,
                                                       w2 + (i - 1) * HH * HH,
                                                       b2 + (i - 1) * HH, hp,
                                                       statsp + i * 2 * HH);
        bn_coef_kernel<<<1, 64>>>(statsp + i * 2 * HH, gam + i * HH, bet + i * HH,
                                  scp + i * HH, sfp + i * HH);
    }

    pool_kernel<<<(NN + 255) / 256, 256>>>(hp, batch, scp + 3 * HH, sfp + 3 * HH);
    head_kernel<<<GG, 128>>>(hw1, hb1, hw2, hb2, out);
}

// round 4
// speedup vs baseline: 1.5366x; 1.3118x over previous
#include <cuda_runtime.h>

#define NN 100000
#define EE 1600000
#define DIN_ 32
#define HH 64
#define GG 128
#define OUTC 10

typedef unsigned long long u64;

// ---------------- scratch ----------------
__device__ float g_h [(size_t)NN * HH];       // layer output (pre-BN "hraw")
__device__ float g_agg[(size_t)NN * HH];
__device__ float g_eas[(size_t)EE * 16];      // edge_attr in CSR order
__device__ int   g_srcs[EE];
__device__ int   g_rowptr[NN + 1];
__device__ int   g_cur[NN];
__device__ float g_stats[4 * 2 * HH];
__device__ float g_bnsc[4 * HH];
__device__ float g_bnsf[4 * HH];
__device__ float g_pool[GG * HH];
__device__ float g_cnt[GG];

// ---------------- f32x2 helpers ----------------
__device__ __forceinline__ u64 ffma2(u64 a, u64 b, u64 c) {
    u64 d; asm("fma.rn.f32x2 %0, %1, %2, %3;" : "=l"(d) : "l"(a), "l"(b), "l"(c)); return d;
}
__device__ __forceinline__ u64 fmul2(u64 a, u64 b) {
    u64 d; asm("mul.rn.f32x2 %0, %1, %2;" : "=l"(d) : "l"(a), "l"(b)); return d;
}
__device__ __forceinline__ void unpk2(u64 v, float& lo, float& hi) {
    asm("mov.b64 {%0, %1}, %2;" : "=f"(lo), "=f"(hi) : "l"(v));
}

// ---------------- CSR build ----------------
__global__ void hist_kernel(const int* __restrict__ eidx) {
    int e = blockIdx.x * blockDim.x + threadIdx.x;
    if (e < EE) atomicAdd(&g_cur[eidx[EE + e]], 1);
}

__global__ void __launch_bounds__(1024) scan_kernel() {
    int t = threadIdx.x;
    int sum = 0;
    if (t < 1000) {
        const int4* p = (const int4*)(g_cur + t * 100);
#pragma unroll 5
        for (int q = 0; q < 25; q++) { int4 v = p[q]; sum += v.x + v.y + v.z + v.w; }
    }
    int lane = t & 31, wid = t >> 5;
    int inc = sum;
#pragma unroll
    for (int d = 1; d < 32; d <<= 1) {
        int n = __shfl_up_sync(0xffffffffu, inc, d);
        if (lane >= d) inc += n;
    }
    __shared__ int wsum[32];
    if (lane == 31) wsum[wid] = inc;
    __syncthreads();
    if (wid == 0) {
        int wv = wsum[lane];
        int winc = wv;
#pragma unroll
        for (int d = 1; d < 32; d <<= 1) {
            int n = __shfl_up_sync(0xffffffffu, winc, d);
            if (lane >= d) winc += n;
        }
        wsum[lane] = winc - wv;
    }
    __syncthreads();
    if (t < 1000) {
        int run = inc - sum + wsum[wid];
        const int4* p = (const int4*)(g_cur + t * 100);
#pragma unroll 5
        for (int q = 0; q < 25; q++) {
            int4 v = p[q];
            int i = t * 100 + q * 4;
            int4 r; r.x = run; run += v.x; r.y = run; run += v.y;
            r.z = run; run += v.z; r.w = run; run += v.w;
            *(int4*)(g_rowptr + i) = r;
            *(int4*)(g_cur + i) = r;
        }
    }
    if (t == 1023) g_rowptr[NN] = EE;
}

__global__ void scatter_kernel(const int* __restrict__ eidx, const float* __restrict__ ea) {
    int e = blockIdx.x * blockDim.x + threadIdx.x;
    if (e >= EE) return;
    int d = eidx[EE + e];
    int pos = atomicAdd(&g_cur[d], 1);
    g_srcs[pos] = eidx[e];
    const float4* s4 = (const float4*)(ea + (size_t)e * 16);
    float4* d4 = (float4*)(g_eas + (size_t)pos * 16);
    d4[0] = s4[0]; d4[1] = s4[1]; d4[2] = s4[2]; d4[3] = s4[3];
}

// ---------------- layer-0 aggregation (C=32) ----------------
// warp/node; chunks of 8 edges: coop attr staging (1 LDG.128/lane/chunk) +
// 8-deep batched gathers; compute from smem broadcast.
__global__ void __launch_bounds__(128) agg32_kernel(
    const float* __restrict__ xin, const float* __restrict__ ew,
    const float* __restrict__ ebv, float* __restrict__ agg)
{
    __shared__ __align__(16) float sattr[4][8 * 16];
    int wip = threadIdx.x >> 5;
    int warp = blockIdx.x * 4 + wip;
    if (warp >= NN) return;
    int lane = threadIdx.x & 31;
    float* sa = sattr[wip];

    u64 W[8];
    {
        const ulonglong2* wp = (const ulonglong2*)(ew + lane * 16);
#pragma unroll
        for (int q = 0; q < 4; q++) { ulonglong2 v = wp[q]; W[2*q] = v.x; W[2*q+1] = v.y; }
    }
    float eb = ebv[lane];
    int start = g_rowptr[warp], end = g_rowptr[warp + 1];
    float A = 0.f;

    for (int j0 = start; j0 < end; j0 += 8) {
        int m = end - j0; if (m > 8) m = 8;
        if (lane < m * 4)
            ((float4*)sa)[lane] = ((const float4*)(g_eas + (size_t)j0 * 16))[lane];
        float xs[8];
#pragma unroll
        for (int e = 0; e < 8; e++) {
            if (e < m) {
                int s = g_srcs[j0 + e];
                xs[e] = xin[(size_t)s * 32 + lane];
            } else xs[e] = 0.f;
        }
        __syncwarp();
#pragma unroll
        for (int e = 0; e < 8; e++) {
            if (e < m) {
                const ulonglong2* ap = (const ulonglong2*)(sa + e * 16);
                ulonglong2 q0 = ap[0], q1 = ap[1], q2 = ap[2], q3 = ap[3];
                u64 acc = fmul2(q0.x, W[0]);
                acc = ffma2(q0.y, W[1], acc);
                acc = ffma2(q1.x, W[2], acc);
                acc = ffma2(q1.y, W[3], acc);
                acc = ffma2(q2.x, W[4], acc);
                acc = ffma2(q2.y, W[5], acc);
                acc = ffma2(q3.x, W[6], acc);
                acc = ffma2(q3.y, W[7], acc);
                float lo, hi; unpk2(acc, lo, hi);
                A += fmaxf(xs[e] + eb + lo + hi, 0.f);
            }
        }
        __syncwarp();
    }
    agg[(size_t)warp * 32 + lane] = xin[(size_t)warp * 32 + lane] + A;
}

// ---------------- layers 1-3 aggregation (C=64, BN+relu folded) ----------------
__global__ void __launch_bounds__(128) agg64_kernel(
    const float* __restrict__ hraw, const float* __restrict__ ew,
    const float* __restrict__ ebv, const float* __restrict__ bnsc,
    const float* __restrict__ bnsf, float* __restrict__ agg)
{
    __shared__ __align__(16) float sattr[4][8 * 16];
    int wip = threadIdx.x >> 5;
    int warp = blockIdx.x * 4 + wip;
    if (warp >= NN) return;
    int lane = threadIdx.x & 31;
    int c0 = lane * 2;
    float* sa = sattr[wip];

    u64 W0[8], W1[8];
    {
        const ulonglong2* wp = (const ulonglong2*)(ew + c0 * 16);  // rows c0, c0+1 contiguous
#pragma unroll
        for (int q = 0; q < 4; q++) {
            ulonglong2 v0 = wp[q];     W0[2*q] = v0.x; W0[2*q+1] = v0.y;
            ulonglong2 v1 = wp[q + 4]; W1[2*q] = v1.x; W1[2*q+1] = v1.y;
        }
    }
    float eb0 = ebv[c0], eb1 = ebv[c0 + 1];
    float sc0 = bnsc[c0], sc1 = bnsc[c0 + 1];
    float sf0 = bnsf[c0], sf1 = bnsf[c0 + 1];
    int start = g_rowptr[warp], end = g_rowptr[warp + 1];
    float A0 = 0.f, A1 = 0.f;

    for (int j0 = start; j0 < end; j0 += 8) {
        int m = end - j0; if (m > 8) m = 8;
        if (lane < m * 4)
            ((float4*)sa)[lane] = ((const float4*)(g_eas + (size_t)j0 * 16))[lane];
        float2 xs[8];
#pragma unroll
        for (int e = 0; e < 8; e++) {
            if (e < m) {
                int s = g_srcs[j0 + e];
                xs[e] = *(const float2*)(hraw + (size_t)s * 64 + c0);
            } else xs[e] = make_float2(0.f, 0.f);
        }
        __syncwarp();
#pragma unroll
        for (int e = 0; e < 8; e++) {
            if (e < m) {
                const ulonglong2* ap = (const ulonglong2*)(sa + e * 16);
                ulonglong2 q0 = ap[0], q1 = ap[1], q2 = ap[2], q3 = ap[3];
                u64 P0 = q0.x, P1 = q0.y, P2 = q1.x, P3 = q1.y;
                u64 P4 = q2.x, P5 = q2.y, P6 = q3.x, P7 = q3.y;
                u64 acc0 = fmul2(P0, W0[0]);
                u64 acc1 = fmul2(P0, W1[0]);
                acc0 = ffma2(P1, W0[1], acc0); acc1 = ffma2(P1, W1[1], acc1);
                acc0 = ffma2(P2, W0[2], acc0); acc1 = ffma2(P2, W1[2], acc1);
                acc0 = ffma2(P3, W0[3], acc0); acc1 = ffma2(P3, W1[3], acc1);
                acc0 = ffma2(P4, W0[4], acc0); acc1 = ffma2(P4, W1[4], acc1);
                acc0 = ffma2(P5, W0[5], acc0); acc1 = ffma2(P5, W1[5], acc1);
                acc0 = ffma2(P6, W0[6], acc0); acc1 = ffma2(P6, W1[6], acc1);
                acc0 = ffma2(P7, W0[7], acc0); acc1 = ffma2(P7, W1[7], acc1);
                float l0, h0, l1, h1;
                unpk2(acc0, l0, h0); unpk2(acc1, l1, h1);
                float x0 = fmaxf(fmaf(xs[e].x, sc0, sf0), 0.f);
                float x1 = fmaxf(fmaf(xs[e].y, sc1, sf1), 0.f);
                A0 += fmaxf(x0 + eb0 + l0 + h0, 0.f);
                A1 += fmaxf(x1 + eb1 + l1 + h1, 0.f);
            }
        }
        __syncwarp();
    }
    float2 xn = *(const float2*)(hraw + (size_t)warp * 64 + c0);
    float2 o;
    o.x = fmaxf(fmaf(xn.x, sc0, sf0), 0.f) + A0;
    o.y = fmaxf(fmaf(xn.y, sc1, sf1), 0.f) + A1;
    *(float2*)(agg + (size_t)warp * 64 + c0) = o;
}

// ---------------- fused node MLP + BN stats ----------------
template <int K>
__global__ void __launch_bounds__(256) gemm_fused_kernel(
    const float* __restrict__ in, const float* __restrict__ w1,
    const float* __restrict__ b1, const float* __restrict__ w2,
    const float* __restrict__ b2, float* __restrict__ out,
    float* __restrict__ stats)
{
    __shared__ __align__(16) float a_s[64][K + 4];
    __shared__ __align__(16) float w_s[64][68];
    __shared__ __align__(16) float h_s[64][68];
    constexpr int K4 = K / 4;
    int t = threadIdx.x;
    int n0 = blockIdx.x * 64;
    int tx = t & 15, ty = t >> 4;

    for (int i = t; i < 64 * K4; i += 256) {
        int r = i / K4, c4 = i % K4;
        *(float4*)&w_s[r][c4 * 4] = ((const float4*)w1)[i];
        int n = n0 + r;
        float4 v = (n < NN) ? ((const float4*)in)[(size_t)n * K4 + c4] : make_float4(0.f,0.f,0.f,0.f);
        *(float4*)&a_s[r][c4 * 4] = v;
    }
    __syncthreads();

    {
        u64 acc2[4][4] = {};
#pragma unroll
        for (int k = 0; k < K; k += 4) {
            ulonglong2 a[4], b[4];
#pragma unroll
            for (int i = 0; i < 4; i++) a[i] = *(const ulonglong2*)&a_s[ty * 4 + i][k];
#pragma unroll
            for (int j = 0; j < 4; j++) b[j] = *(const ulonglong2*)&w_s[tx + j * 16][k];
#pragma unroll
            for (int i = 0; i < 4; i++)
#pragma unroll
                for (int j = 0; j < 4; j++)
                    acc2[i][j] = ffma2(a[i].x, b[j].x, ffma2(a[i].y, b[j].y, acc2[i][j]));
        }
#pragma unroll
        for (int j = 0; j < 4; j++) {
            int c = tx + j * 16;
            float bb = b1[c];
#pragma unroll
            for (int i = 0; i < 4; i++) {
                float lo, hi; unpk2(acc2[i][j], lo, hi);
                h_s[ty * 4 + i][c] = fmaxf(lo + hi + bb, 0.f);
            }
        }
    }
    __syncthreads();
    for (int i = t; i < 64 * 16; i += 256) {
        int r = i >> 4, c4 = i & 15;
        *(float4*)&w_s[r][c4 * 4] = ((const float4*)w2)[i];
    }
    __syncthreads();

    float val[4][4];
    {
        u64 acc2[4][4] = {};
#pragma unroll
        for (int k = 0; k < 64; k += 4) {
            ulonglong2 a[4], b[4];
#pragma unroll
            for (int i = 0; i < 4; i++) a[i] = *(const ulonglong2*)&h_s[ty * 4 + i][k];
#pragma unroll
            for (int j = 0; j < 4; j++) b[j] = *(const ulonglong2*)&w_s[tx + j * 16][k];
#pragma unroll
            for (int i = 0; i < 4; i++)
#pragma unroll
                for (int j = 0; j < 4; j++)
                    acc2[i][j] = ffma2(a[i].x, b[j].x, ffma2(a[i].y, b[j].y, acc2[i][j]));
        }
#pragma unroll
        for (int j = 0; j < 4; j++) {
            int c = tx + j * 16;
            float bb = b2[c];
#pragma unroll
            for (int i = 0; i < 4; i++) {
                float lo, hi; unpk2(acc2[i][j], lo, hi);
                val[i][j] = fmaxf(lo + hi + bb, 0.f);
            }
        }
    }
    __syncthreads();

    float* redS = &a_s[0][0];
    float* redQ = &h_s[0][0];
#pragma unroll
    for (int j = 0; j < 4; j++) {
        int c = tx + j * 16;
        float s = 0.f, q = 0.f;
#pragma unroll
        for (int i = 0; i < 4; i++) {
            int n = n0 + ty * 4 + i;
            if (n < NN) {
                float v = val[i][j];
                out[(size_t)n * 64 + c] = v;
                s += v; q = fmaf(v, v, q);
            }
        }
        redS[ty * 64 + c] = s;
        redQ[ty * 64 + c] = q;
    }
    __syncthreads();
    if (t < 64) {
        float S = 0.f, Q = 0.f;
#pragma unroll
        for (int r = 0; r < 16; r++) { S += redS[r * 64 + t]; Q += redQ[r * 64 + t]; }
        atomicAdd(&stats[t], S);
        atomicAdd(&stats[64 + t], Q);
    }
}

// ---------------- BN coefficients ----------------
__global__ void bn_coef_kernel(const float* __restrict__ stats,
                               const float* __restrict__ gamma, const float* __restrict__ beta,
                               float* __restrict__ sc, float* __restrict__ sf) {
    int t = threadIdx.x;
    float mu = stats[t] * (1.0f / NN);
    float var = stats[64 + t] * (1.0f / NN) - mu * mu;
    float inv = rsqrtf(var + 1e-5f);
    float g = gamma[t], b = beta[t];
    sc[t] = inv * g;
    sf[t] = b - mu * inv * g;
}

// ---------------- pool (BN of last layer folded; batch sorted) ----------------
__global__ void pool_kernel(const float* __restrict__ hraw, const int* __restrict__ batch,
                            const float* __restrict__ bnsc, const float* __restrict__ bnsf) {
    int warp = blockIdx.x * (blockDim.x >> 5) + (threadIdx.x >> 5);
    int lane = threadIdx.x & 31;
    int base = warp * 32;
    if (base >= NN) return;
    int end = min(base + 32, NN);
    int c0 = lane * 2;
    float sc0 = bnsc[c0], sc1 = bnsc[c0 + 1];
    float sf0 = bnsf[c0], sf1 = bnsf[c0 + 1];

    int curb = batch[base];
    float a0 = 0.f, a1 = 0.f, cf = 0.f;
    for (int n = base; n < end; n++) {
        int b = batch[n];
        if (b != curb) {
            atomicAdd(&g_pool[curb * 64 + c0], a0);
            atomicAdd(&g_pool[curb * 64 + c0 + 1], a1);
            if (lane == 0) atomicAdd(&g_cnt[curb], cf);
            a0 = a1 = cf = 0.f;
            curb = b;
        }
        float2 v = *(const float2*)(hraw + (size_t)n * 64 + c0);
        a0 += fmaxf(fmaf(v.x, sc0, sf0), 0.f);
        a1 += fmaxf(fmaf(v.y, sc1, sf1), 0.f);
        cf += 1.f;
    }
    atomicAdd(&g_pool[curb * 64 + c0], a0);
    atomicAdd(&g_pool[curb * 64 + c0 + 1], a1);
    if (lane == 0) atomicAdd(&g_cnt[curb], cf);
}

// ---------------- MLP head ----------------
__global__ void head_kernel(const float* __restrict__ hw1, const float* __restrict__ hb1,
                            const float* __restrict__ hw2, const float* __restrict__ hb2,
                            float* __restrict__ out) {
    int g = blockIdx.x, t = threadIdx.x;
    __shared__ float p[64];
    __shared__ float z[128];
    if (t < 64) {
        float c = g_cnt[g];
        p[t] = g_pool[g * 64 + t] / fmaxf(c, 1.0f);
    }
    __syncthreads();
    float s = hb1[t];
#pragma unroll 8
    for (int k = 0; k < 64; k++) s = fmaf(p[k], hw1[t * 64 + k], s);
    z[t] = fmaxf(s, 0.f);
    __syncthreads();
    if (t < OUTC) {
        float s2 = hb2[t];
#pragma unroll 8
        for (int k = 0; k < 128; k++) s2 = fmaf(z[k], hw2[t * 128 + k], s2);
        out[g * OUTC + t] = s2;
    }
}

// ---------------- launch ----------------
extern "C" void kernel_launch(void* const* d_in, const int* in_sizes, int n_in,
                              void* d_out, int out_size) {
    const float* x     = (const float*)d_in[0];
    const int*   eidx  = (const int*)  d_in[1];
    const float* ea    = (const float*)d_in[2];
    const int*   batch = (const int*)  d_in[3];
    const float* l0_ew = (const float*)d_in[4];
    const float* l0_eb = (const float*)d_in[5];
    const float* l0_w1 = (const float*)d_in[6];
    const float* l0_b1 = (const float*)d_in[7];
    const float* l0_w2 = (const float*)d_in[8];
    const float* l0_b2 = (const float*)d_in[9];
    const float* ew    = (const float*)d_in[10];
    const float* eb    = (const float*)d_in[11];
    const float* w1    = (const float*)d_in[12];
    const float* b1    = (const float*)d_in[13];
    const float* w2    = (const float*)d_in[14];
    const float* b2    = (const float*)d_in[15];
    const float* gam   = (const float*)d_in[16];
    const float* bet   = (const float*)d_in[17];
    const float* hw1   = (const float*)d_in[18];
    const float* hb1   = (const float*)d_in[19];
    const float* hw2   = (const float*)d_in[20];
    const float* hb2   = (const float*)d_in[21];
    float* out = (float*)d_out;

    float *hp, *aggp, *statsp, *scp, *sfp, *poolp, *cntp;
    int *curp;
    cudaGetSymbolAddress((void**)&hp, g_h);
    cudaGetSymbolAddress((void**)&aggp, g_agg);
    cudaGetSymbolAddress((void**)&statsp, g_stats);
    cudaGetSymbolAddress((void**)&scp, g_bnsc);
    cudaGetSymbolAddress((void**)&sfp, g_bnsf);
    cudaGetSymbolAddress((void**)&poolp, g_pool);
    cudaGetSymbolAddress((void**)&cntp, g_cnt);
    cudaGetSymbolAddress((void**)&curp, g_cur);

    cudaMemsetAsync(curp, 0, NN * sizeof(int));
    cudaMemsetAsync(statsp, 0, 4 * 2 * HH * sizeof(float));
    cudaMemsetAsync(poolp, 0, GG * HH * sizeof(float));
    cudaMemsetAsync(cntp, 0, GG * sizeof(float));

    hist_kernel<<<(EE + 255) / 256, 256>>>(eidx);
    scan_kernel<<<1, 1024>>>();
    scatter_kernel<<<(EE + 255) / 256, 256>>>(eidx, ea);

    int agg_blocks = (NN + 3) / 4;

    agg32_kernel<<<agg_blocks, 128>>>(x, l0_ew, l0_eb, aggp);
    gemm_fused_kernel<32><<<(NN + 63) / 64, 256>>>(aggp, l0_w1, l0_b1, l0_w2, l0_b2, hp, statsp);
    bn_coef_kernel<<<1, 64>>>(statsp, gam, bet, scp, sfp);

    for (int i = 1; i < 4; i++) {
        agg64_kernel<<<agg_blocks, 128>>>(hp, ew + (i - 1) * HH * 16, eb + (i - 1) * HH,
                                          scp + (i - 1) * HH, sfp + (i - 1) * HH, aggp);
        gemm_fused_kernel<64><<<(NN + 63) / 64, 256>>>(aggp, w1 + (i - 1) * HH * HH,
                                                       b1 + (i - 1) * HH,
                                                       w2 + (i - 1) * HH * HH,
                                                       b2 + (i - 1) * HH, hp,
                                                       statsp + i * 2 * HH);
        bn_coef_kernel<<<1, 64>>>(statsp + i * 2 * HH, gam + i * HH, bet + i * HH,
                                  scp + i * HH, sfp + i * HH);
    }

    pool_kernel<<<(NN + 255) / 256, 256>>>(hp, batch, scp + 3 * HH, sfp + 3 * HH);
    head_kernel<<<GG, 128>>>(hw1, hb1, hw2, hb2, out);
}

// round 6
// speedup vs baseline: 1.5572x; 1.0134x over previous
#include <cuda_runtime.h>
#include <cstdint>

#define NN 100000
#define EE 1600000
#define DIN_ 32
#define HH 64
#define GG 128
#define OUTC 10

#define AGG_BLOCKS 444
#define AGG_WPB 8
#define AGG_WARPS (AGG_BLOCKS * AGG_WPB)                 // 3552
#define AGG_NPER ((NN + AGG_WARPS - 1) / AGG_WARPS)      // 29

typedef unsigned long long u64;
typedef unsigned int u32;

// ---------------- scratch ----------------
__device__ float g_h [(size_t)NN * HH];       // layer output (pre-BN "hraw")
__device__ float g_agg[(size_t)NN * HH];
__device__ float g_eas[(size_t)EE * 16];      // edge_attr in CSR order
__device__ int   g_srcs[EE];
__device__ int   g_rowptr[NN + 1];
__device__ int   g_cur[NN];
__device__ float g_stats[4 * 2 * HH];
__device__ float g_bnsc[4 * HH];
__device__ float g_bnsf[4 * HH];
__device__ float g_pool[GG * HH];
__device__ float g_cnt[GG];

// ---------------- f32x2 helpers ----------------
__device__ __forceinline__ u64 ffma2(u64 a, u64 b, u64 c) {
    u64 d; asm("fma.rn.f32x2 %0, %1, %2, %3;" : "=l"(d) : "l"(a), "l"(b), "l"(c)); return d;
}
__device__ __forceinline__ u64 fmul2(u64 a, u64 b) {
    u64 d; asm("mul.rn.f32x2 %0, %1, %2;" : "=l"(d) : "l"(a), "l"(b)); return d;
}
__device__ __forceinline__ void unpk2(u64 v, float& lo, float& hi) {
    asm("mov.b64 {%0, %1}, %2;" : "=f"(lo), "=f"(hi) : "l"(v));
}

// ---------------- cp.async helpers ----------------
__device__ __forceinline__ void cp_async16(u32 saddr, const void* gaddr, int pred) {
    asm volatile(
        "{\n\t.reg .pred p;\n\tsetp.ne.b32 p, %2, 0;\n\t"
        "@p cp.async.ca.shared.global [%0], [%1], 16;\n\t}"
        :: "r"(saddr), "l"(gaddr), "r"(pred) : "memory");
}
#define CP_COMMIT() asm volatile("cp.async.commit_group;" ::: "memory")
#define CP_WAIT1()  asm volatile("cp.async.wait_group 1;" ::: "memory")
#define CP_WAIT0()  asm volatile("cp.async.wait_group 0;" ::: "memory")

// ---------------- CSR build ----------------
__global__ void hist_kernel(const int* __restrict__ eidx) {
    int e = blockIdx.x * blockDim.x + threadIdx.x;
    if (e < EE) atomicAdd(&g_cur[eidx[EE + e]], 1);
}

__global__ void __launch_bounds__(1024) scan_kernel() {
    int t = threadIdx.x;
    int sum = 0;
    if (t < 1000) {
        const int4* p = (const int4*)(g_cur + t * 100);
#pragma unroll 5
        for (int q = 0; q < 25; q++) { int4 v = p[q]; sum += v.x + v.y + v.z + v.w; }
    }
    int lane = t & 31, wid = t >> 5;
    int inc = sum;
#pragma unroll
    for (int d = 1; d < 32; d <<= 1) {
        int n = __shfl_up_sync(0xffffffffu, inc, d);
        if (lane >= d) inc += n;
    }
    __shared__ int wsum[32];
    if (lane == 31) wsum[wid] = inc;
    __syncthreads();
    if (wid == 0) {
        int wv = wsum[lane];
        int winc = wv;
#pragma unroll
        for (int d = 1; d < 32; d <<= 1) {
            int n = __shfl_up_sync(0xffffffffu, winc, d);
            if (lane >= d) winc += n;
        }
        wsum[lane] = winc - wv;
    }
    __syncthreads();
    if (t < 1000) {
        int run = inc - sum + wsum[wid];
        const int4* p = (const int4*)(g_cur + t * 100);
#pragma unroll 5
        for (int q = 0; q < 25; q++) {
            int4 v = p[q];
            int i = t * 100 + q * 4;
            int4 r; r.x = run; run += v.x; r.y = run; run += v.y;
            r.z = run; run += v.z; r.w = run; run += v.w;
            *(int4*)(g_rowptr + i) = r;
            *(int4*)(g_cur + i) = r;
        }
    }
    if (t == 1023) g_rowptr[NN] = EE;
}

__global__ void scatter_kernel(const int* __restrict__ eidx, const float* __restrict__ ea) {
    int e = blockIdx.x * blockDim.x + threadIdx.x;
    if (e >= EE) return;
    int d = eidx[EE + e];
    int pos = atomicAdd(&g_cur[d], 1);
    g_srcs[pos] = eidx[e];
    const float4* s4 = (const float4*)(ea + (size_t)e * 16);
    float4* d4 = (float4*)(g_eas + (size_t)pos * 16);
    d4[0] = s4[0]; d4[1] = s4[1]; d4[2] = s4[2]; d4[3] = s4[3];
}

// ---------------- layer-0 aggregation (C=32): persistent streaming ----------------
__global__ void __launch_bounds__(256, 3) agg32_kernel(
    const float* __restrict__ xin, const float* __restrict__ ew,
    const float* __restrict__ ebv, float* __restrict__ agg)
{
    __shared__ __align__(16) float sattr[AGG_WPB][2][128];
    int wip = threadIdx.x >> 5, lane = threadIdx.x & 31;
    int w = blockIdx.x * AGG_WPB + wip;
    int nbeg = w * AGG_NPER;
    if (nbeg >= NN) return;
    int nend = nbeg + AGG_NPER; if (nend > NN) nend = NN;

    u64 W[8];
    {
        const ulonglong2* wp = (const ulonglong2*)(ew + lane * 16);
#pragma unroll
        for (int q = 0; q < 4; q++) { ulonglong2 v = wp[q]; W[2*q] = v.x; W[2*q+1] = v.y; }
    }
    float eb = ebv[lane];

    u32 sb0 = (u32)__cvta_generic_to_shared(&sattr[wip][0][0]);
    u32 sb1 = (u32)__cvta_generic_to_shared(&sattr[wip][1][0]);

    int jbeg = g_rowptr[nbeg], jend = g_rowptr[nend];
    int node = nbeg;
    int next_end = g_rowptr[node + 1];
    float self = xin[(size_t)node * 32 + lane];
    float A = 0.f;

    int j0 = jbeg;
    int m0 = jend - j0; if (m0 > 8) m0 = 8;
    cp_async16(sb0 + lane * 16, g_eas + (size_t)j0 * 16 + lane * 4, lane < 4 * m0);
    CP_COMMIT();
    float xs[8];
#pragma unroll
    for (int e = 0; e < 8; e++)
        xs[e] = (e < m0) ? xin[(size_t)g_srcs[j0 + e] * 32 + lane] : 0.f;

    int b = 0;
    while (j0 < jend) {
        int j1 = j0 + 8;
        int m1 = jend - j1; if (m1 > 8) m1 = 8;
        cp_async16((b ? sb0 : sb1) + lane * 16,
                   g_eas + (size_t)j1 * 16 + lane * 4, lane < 4 * m1);
        CP_COMMIT();
        float xs2[8];
#pragma unroll
        for (int e = 0; e < 8; e++)
            xs2[e] = (e < m1) ? xin[(size_t)g_srcs[j1 + e] * 32 + lane] : 0.f;
        CP_WAIT1();
        __syncwarp();
        const float* cb = b ? &sattr[wip][1][0] : &sattr[wip][0][0];
#pragma unroll
        for (int e = 0; e < 8; e++) {
            if (e < m0) {
                int j = j0 + e;
                while (j >= next_end) {              // uniform across warp
                    agg[(size_t)node * 32 + lane] = self + A;
                    A = 0.f;
                    node++;
                    next_end = g_rowptr[node + 1];
                    self = xin[(size_t)node * 32 + lane];
                }
                const ulonglong2* ap = (const ulonglong2*)(cb + e * 16);
                ulonglong2 q0 = ap[0], q1 = ap[1], q2 = ap[2], q3 = ap[3];
                u64 acc = fmul2(q0.x, W[0]);
                acc = ffma2(q0.y, W[1], acc);
                acc = ffma2(q1.x, W[2], acc);
                acc = ffma2(q1.y, W[3], acc);
                acc = ffma2(q2.x, W[4], acc);
                acc = ffma2(q2.y, W[5], acc);
                acc = ffma2(q3.x, W[6], acc);
                acc = ffma2(q3.y, W[7], acc);
                float lo, hi; unpk2(acc, lo, hi);
                A += fmaxf(xs[e] + eb + lo + hi, 0.f);
            }
        }
        __syncwarp();
        j0 = j1; m0 = m1; b ^= 1;
#pragma unroll
        for (int e = 0; e < 8; e++) xs[e] = xs2[e];
    }
    CP_WAIT0();
    // final flush (also handles trailing zero-degree nodes)
    while (true) {
        agg[(size_t)node * 32 + lane] = self + A;
        A = 0.f;
        node++;
        if (node >= nend) break;
        self = xin[(size_t)node * 32 + lane];
    }
}

// ---------------- layers 1-3 aggregation (C=64, BN+relu folded): persistent -------
__global__ void __launch_bounds__(256, 3) agg64_kernel(
    const float* __restrict__ hraw, const float* __restrict__ ew,
    const float* __restrict__ ebv, const float* __restrict__ bnsc,
    const float* __restrict__ bnsf, float* __restrict__ agg)
{
    __shared__ __align__(16) float sattr[AGG_WPB][2][128];
    int wip = threadIdx.x >> 5, lane = threadIdx.x & 31;
    int w = blockIdx.x * AGG_WPB + wip;
    int nbeg = w * AGG_NPER;
    if (nbeg >= NN) return;
    int nend = nbeg + AGG_NPER; if (nend > NN) nend = NN;
    int c0 = lane * 2;

    u64 W0[8], W1[8];
    {
        const ulonglong2* wp = (const ulonglong2*)(ew + c0 * 16);
#pragma unroll
        for (int q = 0; q < 4; q++) {
            ulonglong2 v0 = wp[q];     W0[2*q] = v0.x; W0[2*q+1] = v0.y;
            ulonglong2 v1 = wp[q + 4]; W1[2*q] = v1.x; W1[2*q+1] = v1.y;
        }
    }
    float eb0 = ebv[c0], eb1 = ebv[c0 + 1];
    float sc0 = bnsc[c0], sc1 = bnsc[c0 + 1];
    float sf0 = bnsf[c0], sf1 = bnsf[c0 + 1];

    u32 sb0 = (u32)__cvta_generic_to_shared(&sattr[wip][0][0]);
    u32 sb1 = (u32)__cvta_generic_to_shared(&sattr[wip][1][0]);

    int jbeg = g_rowptr[nbeg], jend = g_rowptr[nend];
    int node = nbeg;
    int next_end = g_rowptr[node + 1];
    float2 self = *(const float2*)(hraw + (size_t)node * 64 + c0);
    float A0 = 0.f, A1 = 0.f;

    int j0 = jbeg;
    int m0 = jend - j0; if (m0 > 8) m0 = 8;
    cp_async16(sb0 + lane * 16, g_eas + (size_t)j0 * 16 + lane * 4, lane < 4 * m0);
    CP_COMMIT();
    float2 xs[8];
#pragma unroll
    for (int e = 0; e < 8; e++)
        xs[e] = (e < m0) ? *(const float2*)(hraw + (size_t)g_srcs[j0 + e] * 64 + c0)
                         : make_float2(0.f, 0.f);

    int b = 0;
    while (j0 < jend) {
        int j1 = j0 + 8;
        int m1 = jend - j1; if (m1 > 8) m1 = 8;
        cp_async16((b ? sb0 : sb1) + lane * 16,
                   g_eas + (size_t)j1 * 16 + lane * 4, lane < 4 * m1);
        CP_COMMIT();
        float2 xs2[8];
#pragma unroll
        for (int e = 0; e < 8; e++)
            xs2[e] = (e < m1) ? *(const float2*)(hraw + (size_t)g_srcs[j1 + e] * 64 + c0)
                              : make_float2(0.f, 0.f);
        CP_WAIT1();
        __syncwarp();
        const float* cb = b ? &sattr[wip][1][0] : &sattr[wip][0][0];
#pragma unroll
        for (int e = 0; e < 8; e++) {
            if (e < m0) {
                int j = j0 + e;
                while (j >= next_end) {              // uniform across warp
                    float2 o;
                    o.x = fmaxf(fmaf(self.x, sc0, sf0), 0.f) + A0;
                    o.y = fmaxf(fmaf(self.y, sc1, sf1), 0.f) + A1;
                    *(float2*)(agg + (size_t)node * 64 + c0) = o;
                    A0 = A1 = 0.f;
                    node++;
                    next_end = g_rowptr[node + 1];
                    self = *(const float2*)(hraw + (size_t)node * 64 + c0);
                }
                const ulonglong2* ap = (const ulonglong2*)(cb + e * 16);
                ulonglong2 q0 = ap[0], q1 = ap[1], q2 = ap[2], q3 = ap[3];
                u64 acc0 = fmul2(q0.x, W0[0]);
                u64 acc1 = fmul2(q0.x, W1[0]);
                acc0 = ffma2(q0.y, W0[1], acc0); acc1 = ffma2(q0.y, W1[1], acc1);
                acc0 = ffma2(q1.x, W0[2], acc0); acc1 = ffma2(q1.x, W1[2], acc1);
                acc0 = ffma2(q1.y, W0[3], acc0); acc1 = ffma2(q1.y, W1[3], acc1);
                acc0 = ffma2(q2.x, W0[4], acc0); acc1 = ffma2(q2.x, W1[4], acc1);
                acc0 = ffma2(q2.y, W0[5], acc0); acc1 = ffma2(q2.y, W1[5], acc1);
                acc0 = ffma2(q3.x, W0[6], acc0); acc1 = ffma2(q3.x, W1[6], acc1);
                acc0 = ffma2(q3.y, W0[7], acc0); acc1 = ffma2(q3.y, W1[7], acc1);
                float l0, h0, l1, h1;
                unpk2(acc0, l0, h0); unpk2(acc1, l1, h1);
                float x0 = fmaxf(fmaf(xs[e].x, sc0, sf0), 0.f);
                float x1 = fmaxf(fmaf(xs[e].y, sc1, sf1), 0.f);
                A0 += fmaxf(x0 + eb0 + l0 + h0, 0.f);
                A1 += fmaxf(x1 + eb1 + l1 + h1, 0.f);
            }
        }
        __syncwarp();
        j0 = j1; m0 = m1; b ^= 1;
#pragma unroll
        for (int e = 0; e < 8; e++) xs[e] = xs2[e];
    }
    CP_WAIT0();
    while (true) {
        float2 o;
        o.x = fmaxf(fmaf(self.x, sc0, sf0), 0.f) + A0;
        o.y = fmaxf(fmaf(self.y, sc1, sf1), 0.f) + A1;
        *(float2*)(agg + (size_t)node * 64 + c0) = o;
        A0 = A1 = 0.f;
        node++;
        if (node >= nend) break;
        self = *(const float2*)(hraw + (size_t)node * 64 + c0);
    }
}

// ---------------- fused node MLP + BN stats ----------------
template <int K>
__global__ void __launch_bounds__(256) gemm_fused_kernel(
    const float* __restrict__ in, const float* __restrict__ w1,
    const float* __restrict__ b1, const float* __restrict__ w2,
    const float* __restrict__ b2, float* __restrict__ out,
    float* __restrict__ stats)
{
    __shared__ __align__(16) float a_s[64][K + 4];
    __shared__ __align__(16) float w_s[64][68];
    __shared__ __align__(16) float h_s[64][68];
    constexpr int K4 = K / 4;
    int t = threadIdx.x;
    int n0 = blockIdx.x * 64;
    int tx = t & 15, ty = t >> 4;

    for (int i = t; i < 64 * K4; i += 256) {
        int r = i / K4, c4 = i % K4;
        *(float4*)&w_s[r][c4 * 4] = ((const float4*)w1)[i];
        int n = n0 + r;
        float4 v = (n < NN) ? ((const float4*)in)[(size_t)n * K4 + c4] : make_float4(0.f,0.f,0.f,0.f);
        *(float4*)&a_s[r][c4 * 4] = v;
    }
    __syncthreads();

    {
        u64 acc2[4][4] = {};
#pragma unroll
        for (int k = 0; k < K; k += 4) {
            ulonglong2 a[4], b[4];
#pragma unroll
            for (int i = 0; i < 4; i++) a[i] = *(const ulonglong2*)&a_s[ty * 4 + i][k];
#pragma unroll
            for (int j = 0; j < 4; j++) b[j] = *(const ulonglong2*)&w_s[tx + j * 16][k];
#pragma unroll
            for (int i = 0; i < 4; i++)
#pragma unroll
                for (int j = 0; j < 4; j++)
                    acc2[i][j] = ffma2(a[i].x, b[j].x, ffma2(a[i].y, b[j].y, acc2[i][j]));
        }
#pragma unroll
        for (int j = 0; j < 4; j++) {
            int c = tx + j * 16;
            float bb = b1[c];
#pragma unroll
            for (int i = 0; i < 4; i++) {
                float lo, hi; unpk2(acc2[i][j], lo, hi);
                h_s[ty * 4 + i][c] = fmaxf(lo + hi + bb, 0.f);
            }
        }
    }
    __syncthreads();
    for (int i = t; i < 64 * 16; i += 256) {
        int r = i >> 4, c4 = i & 15;
        *(float4*)&w_s[r][c4 * 4] = ((const float4*)w2)[i];
    }
    __syncthreads();

    float val[4][4];
    {
        u64 acc2[4][4] = {};
#pragma unroll
        for (int k = 0; k < 64; k += 4) {
            ulonglong2 a[4], b[4];
#pragma unroll
            for (int i = 0; i < 4; i++) a[i] = *(const ulonglong2*)&h_s[ty * 4 + i][k];
#pragma unroll
            for (int j = 0; j < 4; j++) b[j] = *(const ulonglong2*)&w_s[tx + j * 16][k];
#pragma unroll
            for (int i = 0; i < 4; i++)
#pragma unroll
                for (int j = 0; j < 4; j++)
                    acc2[i][j] = ffma2(a[i].x, b[j].x, ffma2(a[i].y, b[j].y, acc2[i][j]));
        }
#pragma unroll
        for (int j = 0; j < 4; j++) {
            int c = tx + j * 16;
            float bb = b2[c];
#pragma unroll
            for (int i = 0; i < 4; i++) {
                float lo, hi; unpk2(acc2[i][j], lo, hi);
                val[i][j] = fmaxf(lo + hi + bb, 0.f);
            }
        }
    }
    __syncthreads();

    float* redS = &a_s[0][0];
    float* redQ = &h_s[0][0];
#pragma unroll
    for (int j = 0; j < 4; j++) {
        int c = tx + j * 16;
        float s = 0.f, q = 0.f;
#pragma unroll
        for (int i = 0; i < 4; i++) {
            int n = n0 + ty * 4 + i;
            if (n < NN) {
                float v = val[i][j];
                out[(size_t)n * 64 + c] = v;
                s += v; q = fmaf(v, v, q);
            }
        }
        redS[ty * 64 + c] = s;
        redQ[ty * 64 + c] = q;
    }
    __syncthreads();
    if (t < 64) {
        float S = 0.f, Q = 0.f;
#pragma unroll
        for (int r = 0; r < 16; r++) { S += redS[r * 64 + t]; Q += redQ[r * 64 + t]; }
        atomicAdd(&stats[t], S);
        atomicAdd(&stats[64 + t], Q);
    }
}

// ---------------- BN coefficients ----------------
__global__ void bn_coef_kernel(const float* __restrict__ stats,
                               const float* __restrict__ gamma, const float* __restrict__ beta,
                               float* __restrict__ sc, float* __restrict__ sf) {
    int t = threadIdx.x;
    float mu = stats[t] * (1.0f / NN);
    float var = stats[64 + t] * (1.0f / NN) - mu * mu;
    float inv = rsqrtf(var + 1e-5f);
    float g = gamma[t], b = beta[t];
    sc[t] = inv * g;
    sf[t] = b - mu * inv * g;
}

// ---------------- pool (BN of last layer folded; batch sorted) ----------------
__global__ void pool_kernel(const float* __restrict__ hraw, const int* __restrict__ batch,
                            const float* __restrict__ bnsc, const float* __restrict__ bnsf) {
    int warp = blockIdx.x * (blockDim.x >> 5) + (threadIdx.x >> 5);
    int lane = threadIdx.x & 31;
    int base = warp * 32;
    if (base >= NN) return;
    int end = min(base + 32, NN);
    int c0 = lane * 2;
    float sc0 = bnsc[c0], sc1 = bnsc[c0 + 1];
    float sf0 = bnsf[c0], sf1 = bnsf[c0 + 1];

    int curb = batch[base];
    float a0 = 0.f, a1 = 0.f, cf = 0.f;
    for (int n = base; n < end; n++) {
        int b = batch[n];
        if (b != curb) {
            atomicAdd(&g_pool[curb * 64 + c0], a0);
            atomicAdd(&g_pool[curb * 64 + c0 + 1], a1);
            if (lane == 0) atomicAdd(&g_cnt[curb], cf);
            a0 = a1 = cf = 0.f;
            curb = b;
        }
        float2 v = *(const float2*)(hraw + (size_t)n * 64 + c0);
        a0 += fmaxf(fmaf(v.x, sc0, sf0), 0.f);
        a1 += fmaxf(fmaf(v.y, sc1, sf1), 0.f);
        cf += 1.f;
    }
    atomicAdd(&g_pool[curb * 64 + c0], a0);
    atomicAdd(&g_pool[curb * 64 + c0 + 1], a1);
    if (lane == 0) atomicAdd(&g_cnt[curb], cf);
}

// ---------------- MLP head ----------------
__global__ void head_kernel(const float* __restrict__ hw1, const float* __restrict__ hb1,
                            const float* __restrict__ hw2, const float* __restrict__ hb2,
                            float* __restrict__ out) {
    int g = blockIdx.x, t = threadIdx.x;
    __shared__ float p[64];
    __shared__ float z[128];
    if (t < 64) {
        float c = g_cnt[g];
        p[t] = g_pool[g * 64 + t] / fmaxf(c, 1.0f);
    }
    __syncthreads();
    float s = hb1[t];
#pragma unroll 8
    for (int k = 0; k < 64; k++) s = fmaf(p[k], hw1[t * 64 + k], s);
    z[t] = fmaxf(s, 0.f);
    __syncthreads();
    if (t < OUTC) {
        float s2 = hb2[t];
#pragma unroll 8
        for (int k = 0; k < 128; k++) s2 = fmaf(z[k], hw2[t * 128 + k], s2);
        out[g * OUTC + t] = s2;
    }
}

// ---------------- launch ----------------
extern "C" void kernel_launch(void* const* d_in, const int* in_sizes, int n_in,
                              void* d_out, int out_size) {
    const float* x     = (const float*)d_in[0];
    const int*   eidx  = (const int*)  d_in[1];
    const float* ea    = (const float*)d_in[2];
    const int*   batch = (const int*)  d_in[3];
    const float* l0_ew = (const float*)d_in[4];
    const float* l0_eb = (const float*)d_in[5];
    const float* l0_w1 = (const float*)d_in[6];
    const float* l0_b1 = (const float*)d_in[7];
    const float* l0_w2 = (const float*)d_in[8];
    const float* l0_b2 = (const float*)d_in[9];
    const float* ew    = (const float*)d_in[10];
    const float* eb    = (const float*)d_in[11];
    const float* w1    = (const float*)d_in[12];
    const float* b1    = (const float*)d_in[13];
    const float* w2    = (const float*)d_in[14];
    const float* b2    = (const float*)d_in[15];
    const float* gam   = (const float*)d_in[16];
    const float* bet   = (const float*)d_in[17];
    const float* hw1   = (const float*)d_in[18];
    const float* hb1   = (const float*)d_in[19];
    const float* hw2   = (const float*)d_in[20];
    const float* hb2   = (const float*)d_in[21];
    float* out = (float*)d_out;

    float *hp, *aggp, *statsp, *scp, *sfp, *poolp, *cntp;
    int *curp;
    cudaGetSymbolAddress((void**)&hp, g_h);
    cudaGetSymbolAddress((void**)&aggp, g_agg);
    cudaGetSymbolAddress((void**)&statsp, g_stats);
    cudaGetSymbolAddress((void**)&scp, g_bnsc);
    cudaGetSymbolAddress((void**)&sfp, g_bnsf);
    cudaGetSymbolAddress((void**)&poolp, g_pool);
    cudaGetSymbolAddress((void**)&cntp, g_cnt);
    cudaGetSymbolAddress((void**)&curp, g_cur);

    cudaMemsetAsync(curp, 0, NN * sizeof(int));
    cudaMemsetAsync(statsp, 0, 4 * 2 * HH * sizeof(float));
    cudaMemsetAsync(poolp, 0, GG * HH * sizeof(float));
    cudaMemsetAsync(cntp, 0, GG * sizeof(float));

    hist_kernel<<<(EE + 255) / 256, 256>>>(eidx);
    scan_kernel<<<1, 1024>>>();
    scatter_kernel<<<(EE + 255) / 256, 256>>>(eidx, ea);

    agg32_kernel<<<AGG_BLOCKS, 256>>>(x, l0_ew, l0_eb, aggp);
    gemm_fused_kernel<32><<<(NN + 63) / 64, 256>>>(aggp, l0_w1, l0_b1, l0_w2, l0_b2, hp, statsp);
    bn_coef_kernel<<<1, 64>>>(statsp, gam, bet, scp, sfp);

    for (int i = 1; i < 4; i++) {
        agg64_kernel<<<AGG_BLOCKS, 256>>>(hp, ew + (i - 1) * HH * 16, eb + (i - 1) * HH,
                                          scp + (i - 1) * HH, sfp + (i - 1) * HH, aggp);
        gemm_fused_kernel<64><<<(NN + 63) / 64, 256>>>(aggp, w1 + (i - 1) * HH * HH,
                                                       b1 + (i - 1) * HH,
                                                       w2 + (i - 1) * HH * HH,
                                                       b2 + (i - 1) * HH, hp,
                                                       statsp + i * 2 * HH);
        bn_coef_kernel<<<1, 64>>>(statsp + i * 2 * HH, gam + i * HH, bet + i * HH,
                                  scp + i * HH, sfp + i * HH);
    }

    pool_kernel<<<(NN + 255) / 256, 256>>>(hp, batch, scp + 3 * HH, sfp + 3 * HH);
    head_kernel<<<GG, 128>>>(hw1, hb1, hw2, hb2, out);
}